// round 2
// baseline (speedup 1.0000x reference)
#include <cuda_runtime.h>
#include <cuda_bf16.h>
#include <cstdint>

static constexpr int NN  = 8192;
static constexpr int EE  = 524288;
static constexpr int FIN = 128;
static constexpr int FH  = 256;
static constexpr int FO  = 128;

// ---------------- scratch (device globals; no allocation allowed) ----------
__device__ int   g_cnt[NN];
__device__ int   g_cursor[NN];
__device__ int   g_rowstart[NN + 1];
__device__ int   g_src[EE];
__device__ float g_dinv[NN];
__device__ float g_h1[NN * FH];          // lin1 = emb[x] @ W1
__device__ float g_a1[NN * FH];          // relu(gcn1)
__device__ float g_z2[NN * FO];          // lin2 = a1 @ W2
__device__ __nv_bfloat16 g_zb[NN * FO];  // z in bf16 for tensor-core decode

// ---------------- CSR build ------------------------------------------------
__global__ void k_init() {
    int i = blockIdx.x * blockDim.x + threadIdx.x;
    if (i < NN) { g_cnt[i] = 0; g_cursor[i] = 0; }
}

__global__ void k_count(const int* __restrict__ dst) {
    int e = blockIdx.x * blockDim.x + threadIdx.x;
    if (e < EE) atomicAdd(&g_cnt[dst[e]], 1);
}

// one block, 1024 threads, 8 elems/thread: scan counts -> rowstart, dinv
__global__ void __launch_bounds__(1024) k_scan() {
    __shared__ int s[1024];
    int t = threadIdx.x;
    int base = t * 8;
    int v[8]; int sum = 0;
#pragma unroll
    for (int i = 0; i < 8; i++) { v[i] = g_cnt[base + i]; sum += v[i]; }
    s[t] = sum;
    __syncthreads();
    for (int off = 1; off < 1024; off <<= 1) {
        int add = (t >= off) ? s[t - off] : 0;
        __syncthreads();
        s[t] += add;
        __syncthreads();
    }
    int run = s[t] - sum;  // exclusive prefix
#pragma unroll
    for (int i = 0; i < 8; i++) {
        g_rowstart[base + i] = run;
        run += v[i];
        g_dinv[base + i] = rsqrtf((float)v[i] + 1.0f);  // +1 self loop
    }
    if (t == 1023) g_rowstart[NN] = run;
}

__global__ void k_fill(const int* __restrict__ src, const int* __restrict__ dst) {
    int e = blockIdx.x * blockDim.x + threadIdx.x;
    if (e < EE) {
        int d = dst[e];
        int p = atomicAdd(&g_cursor[d], 1);
        g_src[g_rowstart[d] + p] = src[e];
    }
}

// ---------------- lin1: g_h1 = emb[x] @ W1  (16 nodes / block) -------------
__global__ void __launch_bounds__(256) k_lin1(const int* __restrict__ x,
                                              const float* __restrict__ emb,
                                              const float* __restrict__ W1) {
    __shared__ float se[16][FIN];
    __shared__ int   sx[16];
    int t = threadIdx.x;
    int n0 = blockIdx.x * 16;
    if (t < 16) sx[t] = x[n0 + t];
    __syncthreads();
    for (int i = t; i < 16 * FIN; i += 256) {
        int r = i >> 7, k = i & 127;
        se[r][k] = emb[sx[r] * FIN + k];
    }
    __syncthreads();
    float acc[16];
#pragma unroll
    for (int r = 0; r < 16; r++) acc[r] = 0.f;
    const float* w = W1 + t;  // column t, coalesced across threads
    for (int k = 0; k < FIN; k++) {
        float wv = w[k * FH];
#pragma unroll
        for (int r = 0; r < 16; r++) acc[r] = fmaf(se[r][k], wv, acc[r]);
    }
#pragma unroll
    for (int r = 0; r < 16; r++) g_h1[(n0 + r) * FH + t] = acc[r];
}

// ---------------- lin2: g_z2 = a1 @ W2 (16 nodes / block, 128 threads) -----
__global__ void __launch_bounds__(128) k_lin2(const float* __restrict__ W2) {
    __shared__ float sa[16][FH];
    int t = threadIdx.x;
    int n0 = blockIdx.x * 16;
    for (int i = t; i < 16 * FH; i += 128) {
        int r = i >> 8, k = i & 255;
        sa[r][k] = g_a1[(n0 + r) * FH + k];
    }
    __syncthreads();
    float acc[16];
#pragma unroll
    for (int r = 0; r < 16; r++) acc[r] = 0.f;
    for (int k = 0; k < FH; k++) {
        float wv = W2[k * FO + t];
#pragma unroll
        for (int r = 0; r < 16; r++) acc[r] = fmaf(sa[r][k], wv, acc[r]);
    }
#pragma unroll
    for (int r = 0; r < 16; r++) g_z2[(n0 + r) * FO + t] = acc[r];
}

// ---------------- GCN aggregation (CSR gather, one block per node) ---------
// agg[d] = dinv[d] * sum_e dinv[src]*hlin[src] + dinv[d]^2 * hlin[d] + bias
template <bool LAYER1>
__global__ void k_agg(const float* __restrict__ bias) {
    constexpr int F = LAYER1 ? FH : FO;
    const float* __restrict__ hlin = LAYER1 ? g_h1 : g_z2;
    int d = blockIdx.x;
    int f = threadIdx.x;
    int i = g_rowstart[d], end = g_rowstart[d + 1];
    float acc = 0.f;
    for (; i + 4 <= end; i += 4) {
        int s0 = g_src[i], s1 = g_src[i + 1], s2 = g_src[i + 2], s3 = g_src[i + 3];
        float p0 = g_dinv[s0] * hlin[s0 * F + f];
        float p1 = g_dinv[s1] * hlin[s1 * F + f];
        float p2 = g_dinv[s2] * hlin[s2 * F + f];
        float p3 = g_dinv[s3] * hlin[s3 * F + f];
        acc += (p0 + p1) + (p2 + p3);
    }
    for (; i < end; i++) {
        int s0 = g_src[i];
        acc += g_dinv[s0] * hlin[s0 * F + f];
    }
    float dd = g_dinv[d];
    float r = fmaf(dd, acc, dd * dd * hlin[d * F + f]) + bias[f];
    if (LAYER1) {
        g_a1[d * F + f] = fmaxf(r, 0.f);
    } else {
        g_zb[d * F + f] = __float2bfloat16(r);
    }
}

// ---------------- decode: out = sigmoid(z @ z^T), bf16 mma ----------------
__device__ __forceinline__ float sigmoidf_(float v) {
    return 1.0f / (1.0f + __expf(-v));
}

__device__ __forceinline__ uint32_t smem_u32(const void* p) {
    return (uint32_t)__cvta_generic_to_shared(p);
}

// 128x128 tile per block, 256 threads (8 warps, warp tile 32x64), K=128.
__global__ void __launch_bounds__(256) k_decode(float* __restrict__ out) {
    constexpr int P = 136;  // bf16 pitch, conflict-free ldmatrix
    extern __shared__ __nv_bfloat16 sm[];
    __nv_bfloat16* sA = sm;
    __nv_bfloat16* sB = sm + 128 * P;

    int t  = threadIdx.x;
    int i0 = blockIdx.y * 128;
    int j0 = blockIdx.x * 128;

    // cooperative load of A (rows i0..) and B (rows j0..), 16B vectors.
    // 128 rows x 128 bf16 = 128 x 16 uint4 per tile; 2 tiles = 4096 vectors.
    for (int v = t; v < 4096; v += 256) {
        int which = v >> 11;               // 0 = A, 1 = B
        int r = (v >> 4) & 127;
        int c = (v & 15) * 8;
        const __nv_bfloat16* srcp = g_zb + (size_t)((which ? j0 : i0) + r) * FO + c;
        __nv_bfloat16* dstp = (which ? sB : sA) + r * P + c;
        *(uint4*)dstp = *(const uint4*)srcp;
    }
    __syncthreads();

    int lane = t & 31, w = t >> 5;
    int wm = (w & 3) * 32;   // warp row offset within tile
    int wn = (w >> 2) * 64;  // warp col offset within tile

    float acc[2][8][4];
#pragma unroll
    for (int mt = 0; mt < 2; mt++)
#pragma unroll
        for (int nt = 0; nt < 8; nt++)
#pragma unroll
            for (int q = 0; q < 4; q++) acc[mt][nt][q] = 0.f;

#pragma unroll
    for (int ks = 0; ks < 8; ks++) {
        int k0 = ks * 16;
        uint32_t a[2][4];
#pragma unroll
        for (int mt = 0; mt < 2; mt++) {
            const __nv_bfloat16* p = sA + (wm + mt * 16 + (lane & 15)) * P
                                        + k0 + (lane >> 4) * 8;
            uint32_t addr = smem_u32(p);
            asm volatile("ldmatrix.sync.aligned.m8n8.x4.shared.b16 {%0,%1,%2,%3}, [%4];"
                         : "=r"(a[mt][0]), "=r"(a[mt][1]), "=r"(a[mt][2]), "=r"(a[mt][3])
                         : "r"(addr));
        }
        uint32_t b[8][2];
#pragma unroll
        for (int pr = 0; pr < 4; pr++) {
            const __nv_bfloat16* p = sB + (wn + pr * 16 + (lane >> 4) * 8 + (lane & 7)) * P
                                        + k0 + ((lane >> 3) & 1) * 8;
            uint32_t addr = smem_u32(p);
            asm volatile("ldmatrix.sync.aligned.m8n8.x4.shared.b16 {%0,%1,%2,%3}, [%4];"
                         : "=r"(b[2 * pr][0]), "=r"(b[2 * pr][1]),
                           "=r"(b[2 * pr + 1][0]), "=r"(b[2 * pr + 1][1])
                         : "r"(addr));
        }
#pragma unroll
        for (int mt = 0; mt < 2; mt++)
#pragma unroll
            for (int nt = 0; nt < 8; nt++)
                asm volatile(
                    "mma.sync.aligned.m16n8k16.row.col.f32.bf16.bf16.f32 "
                    "{%0,%1,%2,%3}, {%4,%5,%6,%7}, {%8,%9}, {%0,%1,%2,%3};"
                    : "+f"(acc[mt][nt][0]), "+f"(acc[mt][nt][1]),
                      "+f"(acc[mt][nt][2]), "+f"(acc[mt][nt][3])
                    : "r"(a[mt][0]), "r"(a[mt][1]), "r"(a[mt][2]), "r"(a[mt][3]),
                      "r"(b[nt][0]), "r"(b[nt][1]));
    }

    // epilogue: sigmoid + store (float2 per fragment row)
#pragma unroll
    for (int mt = 0; mt < 2; mt++) {
        int row = i0 + wm + mt * 16 + (lane >> 2);
#pragma unroll
        for (int nt = 0; nt < 8; nt++) {
            int col = j0 + wn + nt * 8 + (lane & 3) * 2;
            float2 v0 = make_float2(sigmoidf_(acc[mt][nt][0]), sigmoidf_(acc[mt][nt][1]));
            float2 v1 = make_float2(sigmoidf_(acc[mt][nt][2]), sigmoidf_(acc[mt][nt][3]));
            *(float2*)(out + (size_t)row * NN + col)       = v0;
            *(float2*)(out + (size_t)(row + 8) * NN + col) = v1;
        }
    }
}

// ---------------- launch ----------------------------------------------------
extern "C" void kernel_launch(void* const* d_in, const int* in_sizes, int n_in,
                              void* d_out, int out_size) {
    const int*   x   = (const int*)d_in[0];
    const int*   ei  = (const int*)d_in[1];   // [2, E]: src then dst
    const float* emb = (const float*)d_in[2];
    const float* W1  = (const float*)d_in[3];
    const float* b1  = (const float*)d_in[4];
    const float* W2  = (const float*)d_in[5];
    const float* b2  = (const float*)d_in[6];
    float* out = (float*)d_out;

    const int* src = ei;
    const int* dst = ei + EE;

    cudaFuncSetAttribute(k_decode, cudaFuncAttributeMaxDynamicSharedMemorySize,
                         2 * 128 * 136 * (int)sizeof(__nv_bfloat16));

    k_init <<<NN / 256, 256>>>();
    k_count<<<EE / 256, 256>>>(dst);
    k_scan <<<1, 1024>>>();
    k_fill <<<EE / 256, 256>>>(src, dst);

    k_lin1<<<NN / 16, 256>>>(x, emb, W1);
    k_agg<true> <<<NN, FH>>>(b1);
    k_lin2<<<NN / 16, 128>>>(W2);
    k_agg<false><<<NN, FO>>>(b2);

    dim3 grid(NN / 128, NN / 128);
    k_decode<<<grid, 256, 2 * 128 * 136 * (int)sizeof(__nv_bfloat16)>>>(out);
}

// round 3
// speedup vs baseline: 1.0857x; 1.0857x over previous
#include <cuda_runtime.h>
#include <cuda_bf16.h>
#include <cstdint>

static constexpr int NN  = 8192;
static constexpr int EE  = 524288;
static constexpr int FIN = 128;
static constexpr int FH  = 256;
static constexpr int FO  = 128;

// ---------------- scratch (device globals; no allocation allowed) ----------
__device__ int   g_cnt[NN];
__device__ int   g_cursor[NN];
__device__ int   g_rowstart[NN + 1];
__device__ int   g_src[EE];
__device__ float g_dinv[NN];
__device__ __nv_bfloat16 g_h1b[NN * FH];  // lin1 = emb[x] @ W1  (bf16)
__device__ float g_a1[NN * FH];           // relu(gcn1)          (fp32)
__device__ __nv_bfloat16 g_z2b[NN * FO];  // lin2 = a1 @ W2      (bf16)
__device__ __nv_bfloat16 g_zb[NN * FO];   // z (gcn2 out)        (bf16)

// ---------------- CSR build ------------------------------------------------
__global__ void k_init() {
    int i = blockIdx.x * blockDim.x + threadIdx.x;
    if (i < NN) { g_cnt[i] = 0; g_cursor[i] = 0; }
}

__global__ void k_count(const int* __restrict__ dst) {
    int e = blockIdx.x * blockDim.x + threadIdx.x;
    if (e < EE) atomicAdd(&g_cnt[dst[e]], 1);
}

// one block, 1024 threads, 8 elems/thread: scan counts -> rowstart, dinv
__global__ void __launch_bounds__(1024) k_scan() {
    __shared__ int s[1024];
    int t = threadIdx.x;
    int base = t * 8;
    int v[8]; int sum = 0;
#pragma unroll
    for (int i = 0; i < 8; i++) { v[i] = g_cnt[base + i]; sum += v[i]; }
    s[t] = sum;
    __syncthreads();
    for (int off = 1; off < 1024; off <<= 1) {
        int add = (t >= off) ? s[t - off] : 0;
        __syncthreads();
        s[t] += add;
        __syncthreads();
    }
    int run = s[t] - sum;  // exclusive prefix
#pragma unroll
    for (int i = 0; i < 8; i++) {
        g_rowstart[base + i] = run;
        run += v[i];
        g_dinv[base + i] = rsqrtf((float)v[i] + 1.0f);  // +1 self loop
    }
    if (t == 1023) g_rowstart[NN] = run;
}

__global__ void k_fill(const int* __restrict__ src, const int* __restrict__ dst) {
    int e = blockIdx.x * blockDim.x + threadIdx.x;
    if (e < EE) {
        int d = dst[e];
        int p = atomicAdd(&g_cursor[d], 1);
        g_src[g_rowstart[d] + p] = src[e];
    }
}

// ---------------- lin1: g_h1b = emb[x] @ W1  (16 nodes / block) ------------
__global__ void __launch_bounds__(256) k_lin1(const int* __restrict__ x,
                                              const float* __restrict__ emb,
                                              const float* __restrict__ W1) {
    __shared__ float se[16][FIN];
    __shared__ int   sx[16];
    int t = threadIdx.x;
    int n0 = blockIdx.x * 16;
    if (t < 16) sx[t] = x[n0 + t];
    __syncthreads();
    for (int i = t; i < 16 * FIN; i += 256) {
        int r = i >> 7, k = i & 127;
        se[r][k] = emb[sx[r] * FIN + k];
    }
    __syncthreads();
    float acc[16];
#pragma unroll
    for (int r = 0; r < 16; r++) acc[r] = 0.f;
    const float* w = W1 + t;  // column t, coalesced across threads
    for (int k = 0; k < FIN; k++) {
        float wv = w[k * FH];
#pragma unroll
        for (int r = 0; r < 16; r++) acc[r] = fmaf(se[r][k], wv, acc[r]);
    }
#pragma unroll
    for (int r = 0; r < 16; r++)
        g_h1b[(n0 + r) * FH + t] = __float2bfloat16(acc[r]);
}

// ---------------- lin2: g_z2b = a1 @ W2 (16 nodes / block, 128 threads) ----
__global__ void __launch_bounds__(128) k_lin2(const float* __restrict__ W2) {
    __shared__ float sa[16][FH];
    int t = threadIdx.x;
    int n0 = blockIdx.x * 16;
    for (int i = t; i < 16 * FH; i += 128) {
        int r = i >> 8, k = i & 255;
        sa[r][k] = g_a1[(n0 + r) * FH + k];
    }
    __syncthreads();
    float acc[16];
#pragma unroll
    for (int r = 0; r < 16; r++) acc[r] = 0.f;
    for (int k = 0; k < FH; k++) {
        float wv = W2[k * FO + t];
#pragma unroll
        for (int r = 0; r < 16; r++) acc[r] = fmaf(sa[r][k], wv, acc[r]);
    }
#pragma unroll
    for (int r = 0; r < 16; r++)
        g_z2b[(n0 + r) * FO + t] = __float2bfloat16(acc[r]);
}

// ---------------- GCN aggregation, layer 1 (bf16x2 gathers, fp32 accum) ----
// agg[d] = dinv[d] * sum_e dinv[src]*h[src] + dinv[d]^2 * h[d] + bias; relu
__global__ void __launch_bounds__(128) k_agg1(const float* __restrict__ bias) {
    const __nv_bfloat162* __restrict__ H = (const __nv_bfloat162*)g_h1b;
    int d = blockIdx.x;
    int t = threadIdx.x;          // handles features 2t, 2t+1
    int i = g_rowstart[d], end = g_rowstart[d + 1];
    float ax = 0.f, ay = 0.f;
    for (; i + 4 <= end; i += 4) {
        int s0 = g_src[i], s1 = g_src[i + 1], s2 = g_src[i + 2], s3 = g_src[i + 3];
        float w0 = g_dinv[s0], w1 = g_dinv[s1], w2 = g_dinv[s2], w3 = g_dinv[s3];
        float2 f0 = __bfloat1622float2(H[s0 * 128 + t]);
        float2 f1 = __bfloat1622float2(H[s1 * 128 + t]);
        float2 f2 = __bfloat1622float2(H[s2 * 128 + t]);
        float2 f3 = __bfloat1622float2(H[s3 * 128 + t]);
        ax += w0 * f0.x + w1 * f1.x + w2 * f2.x + w3 * f3.x;
        ay += w0 * f0.y + w1 * f1.y + w2 * f2.y + w3 * f3.y;
    }
    for (; i < end; i++) {
        int s0 = g_src[i];
        float w0 = g_dinv[s0];
        float2 f0 = __bfloat1622float2(H[s0 * 128 + t]);
        ax += w0 * f0.x;
        ay += w0 * f0.y;
    }
    float dd = g_dinv[d];
    float2 hs = __bfloat1622float2(H[d * 128 + t]);
    float2 bb = ((const float2*)bias)[t];
    float rx = fmaf(dd, ax, dd * dd * hs.x) + bb.x;
    float ry = fmaf(dd, ay, dd * dd * hs.y) + bb.y;
    ((float2*)g_a1)[d * 128 + t] = make_float2(fmaxf(rx, 0.f), fmaxf(ry, 0.f));
}

// ---------------- GCN aggregation, layer 2 ----------------------------------
__global__ void __launch_bounds__(64) k_agg2(const float* __restrict__ bias) {
    const __nv_bfloat162* __restrict__ Z = (const __nv_bfloat162*)g_z2b;
    int d = blockIdx.x;
    int t = threadIdx.x;          // handles features 2t, 2t+1 (64 threads)
    int i = g_rowstart[d], end = g_rowstart[d + 1];
    float ax = 0.f, ay = 0.f;
    for (; i + 4 <= end; i += 4) {
        int s0 = g_src[i], s1 = g_src[i + 1], s2 = g_src[i + 2], s3 = g_src[i + 3];
        float w0 = g_dinv[s0], w1 = g_dinv[s1], w2 = g_dinv[s2], w3 = g_dinv[s3];
        float2 f0 = __bfloat1622float2(Z[s0 * 64 + t]);
        float2 f1 = __bfloat1622float2(Z[s1 * 64 + t]);
        float2 f2 = __bfloat1622float2(Z[s2 * 64 + t]);
        float2 f3 = __bfloat1622float2(Z[s3 * 64 + t]);
        ax += w0 * f0.x + w1 * f1.x + w2 * f2.x + w3 * f3.x;
        ay += w0 * f0.y + w1 * f1.y + w2 * f2.y + w3 * f3.y;
    }
    for (; i < end; i++) {
        int s0 = g_src[i];
        float w0 = g_dinv[s0];
        float2 f0 = __bfloat1622float2(Z[s0 * 64 + t]);
        ax += w0 * f0.x;
        ay += w0 * f0.y;
    }
    float dd = g_dinv[d];
    float2 zs = __bfloat1622float2(Z[d * 64 + t]);
    float2 bb = ((const float2*)bias)[t];
    float rx = fmaf(dd, ax, dd * dd * zs.x) + bb.x;
    float ry = fmaf(dd, ay, dd * dd * zs.y) + bb.y;
    ((__nv_bfloat162*)g_zb)[d * 64 + t] = __floats2bfloat162_rn(rx, ry);
}

// ---------------- decode: out = sigmoid(z @ z^T), bf16 mma, symmetric ------
__device__ __forceinline__ float sigmoidf_(float v) {
    return 1.0f / (1.0f + __expf(-v));
}

__device__ __forceinline__ uint32_t smem_u32(const void* p) {
    return (uint32_t)__cvta_generic_to_shared(p);
}

// 128x128 tile per block, 256 threads (8 warps, warp tile 32x64), K=128.
// Only computes tiles with bj >= bi; mirrors off-diagonal tiles through a
// shared-memory transpose (output is symmetric).
__global__ void __launch_bounds__(256) k_decode(float* __restrict__ out) {
    int bi = blockIdx.y, bj = blockIdx.x;
    if (bj < bi) return;

    constexpr int P  = 136;  // bf16 pitch, conflict-free ldmatrix
    constexpr int PT = 132;  // fp32 pitch for transpose staging
    extern __shared__ __nv_bfloat16 sm[];
    __nv_bfloat16* sA = sm;
    __nv_bfloat16* sB = sm + 128 * P;
    float* sf = (float*)sm;  // reused after MMA (67584 B <= 69632 B)

    int t  = threadIdx.x;
    int i0 = bi * 128;
    int j0 = bj * 128;

    // cooperative load: 2 tiles x 128 rows x 16 uint4
    for (int v = t; v < 4096; v += 256) {
        int which = v >> 11;               // 0 = A, 1 = B
        int r = (v >> 4) & 127;
        int c = (v & 15) * 8;
        const __nv_bfloat16* srcp = g_zb + (size_t)((which ? j0 : i0) + r) * FO + c;
        __nv_bfloat16* dstp = (which ? sB : sA) + r * P + c;
        *(uint4*)dstp = *(const uint4*)srcp;
    }
    __syncthreads();

    int lane = t & 31, w = t >> 5;
    int wm = (w & 3) * 32;   // warp row offset within tile
    int wn = (w >> 2) * 64;  // warp col offset within tile

    float acc[2][8][4];
#pragma unroll
    for (int mt = 0; mt < 2; mt++)
#pragma unroll
        for (int nt = 0; nt < 8; nt++)
#pragma unroll
            for (int q = 0; q < 4; q++) acc[mt][nt][q] = 0.f;

#pragma unroll
    for (int ks = 0; ks < 8; ks++) {
        int k0 = ks * 16;
        uint32_t a[2][4];
#pragma unroll
        for (int mt = 0; mt < 2; mt++) {
            const __nv_bfloat16* p = sA + (wm + mt * 16 + (lane & 15)) * P
                                        + k0 + (lane >> 4) * 8;
            uint32_t addr = smem_u32(p);
            asm volatile("ldmatrix.sync.aligned.m8n8.x4.shared.b16 {%0,%1,%2,%3}, [%4];"
                         : "=r"(a[mt][0]), "=r"(a[mt][1]), "=r"(a[mt][2]), "=r"(a[mt][3])
                         : "r"(addr));
        }
        uint32_t b[8][2];
#pragma unroll
        for (int pr = 0; pr < 4; pr++) {
            const __nv_bfloat16* p = sB + (wn + pr * 16 + (lane >> 4) * 8 + (lane & 7)) * P
                                        + k0 + ((lane >> 3) & 1) * 8;
            uint32_t addr = smem_u32(p);
            asm volatile("ldmatrix.sync.aligned.m8n8.x4.shared.b16 {%0,%1,%2,%3}, [%4];"
                         : "=r"(b[2 * pr][0]), "=r"(b[2 * pr][1]),
                           "=r"(b[2 * pr + 1][0]), "=r"(b[2 * pr + 1][1])
                         : "r"(addr));
        }
#pragma unroll
        for (int mt = 0; mt < 2; mt++)
#pragma unroll
            for (int nt = 0; nt < 8; nt++)
                asm volatile(
                    "mma.sync.aligned.m16n8k16.row.col.f32.bf16.bf16.f32 "
                    "{%0,%1,%2,%3}, {%4,%5,%6,%7}, {%8,%9}, {%0,%1,%2,%3};"
                    : "+f"(acc[mt][nt][0]), "+f"(acc[mt][nt][1]),
                      "+f"(acc[mt][nt][2]), "+f"(acc[mt][nt][3])
                    : "r"(a[mt][0]), "r"(a[mt][1]), "r"(a[mt][2]), "r"(a[mt][3]),
                      "r"(b[nt][0]), "r"(b[nt][1]));
    }

    bool diag = (bi == bj);
    if (!diag) __syncthreads();  // done reading sA/sB before staging reuses it

    // epilogue: sigmoid once; direct store; stage for mirror if off-diagonal
#pragma unroll
    for (int mt = 0; mt < 2; mt++) {
        int r0 = wm + mt * 16 + (lane >> 2);
#pragma unroll
        for (int nt = 0; nt < 8; nt++) {
            int c0 = wn + nt * 8 + (lane & 3) * 2;
            float2 v0 = make_float2(sigmoidf_(acc[mt][nt][0]), sigmoidf_(acc[mt][nt][1]));
            float2 v1 = make_float2(sigmoidf_(acc[mt][nt][2]), sigmoidf_(acc[mt][nt][3]));
            *(float2*)(out + (size_t)(i0 + r0) * NN + j0 + c0)     = v0;
            *(float2*)(out + (size_t)(i0 + r0 + 8) * NN + j0 + c0) = v1;
            if (!diag) {
                *(float2*)&sf[r0 * PT + c0]       = v0;
                *(float2*)&sf[(r0 + 8) * PT + c0] = v1;
            }
        }
    }

    if (!diag) {
        __syncthreads();
        // mirror: out[j0+c][i0+r] = tile[r][c]; one warp per mirror row,
        // coalesced float4 global writes.
        for (int idx = t; idx < 4096; idx += 256) {
            int c  = idx >> 5;
            int rq = (idx & 31) * 4;
            float4 v = make_float4(sf[(rq + 0) * PT + c], sf[(rq + 1) * PT + c],
                                   sf[(rq + 2) * PT + c], sf[(rq + 3) * PT + c]);
            *(float4*)(out + (size_t)(j0 + c) * NN + i0 + rq) = v;
        }
    }
}

// ---------------- launch ----------------------------------------------------
extern "C" void kernel_launch(void* const* d_in, const int* in_sizes, int n_in,
                              void* d_out, int out_size) {
    const int*   x   = (const int*)d_in[0];
    const int*   ei  = (const int*)d_in[1];   // [2, E]: src then dst
    const float* emb = (const float*)d_in[2];
    const float* W1  = (const float*)d_in[3];
    const float* b1  = (const float*)d_in[4];
    const float* W2  = (const float*)d_in[5];
    const float* b2  = (const float*)d_in[6];
    float* out = (float*)d_out;

    const int* src = ei;
    const int* dst = ei + EE;

    const int smem = 2 * 128 * 136 * (int)sizeof(__nv_bfloat16);  // 69632
    cudaFuncSetAttribute(k_decode, cudaFuncAttributeMaxDynamicSharedMemorySize, smem);

    k_init <<<NN / 256, 256>>>();
    k_count<<<EE / 256, 256>>>(dst);
    k_scan <<<1, 1024>>>();
    k_fill <<<EE / 256, 256>>>(src, dst);

    k_lin1<<<NN / 16, 256>>>(x, emb, W1);
    k_agg1<<<NN, 128>>>(b1);
    k_lin2<<<NN / 16, 128>>>(W2);
    k_agg2<<<NN, 64>>>(b2);

    dim3 grid(NN / 128, NN / 128);
    k_decode<<<grid, 256, smem>>>(out);
}

// round 4
// speedup vs baseline: 1.2212x; 1.1248x over previous
#include <cuda_runtime.h>
#include <cuda_bf16.h>
#include <cstdint>

static constexpr int NN  = 8192;
static constexpr int EE  = 524288;
static constexpr int FIN = 128;
static constexpr int FH  = 256;
static constexpr int FO  = 128;

// ---------------- scratch (device globals; no allocation allowed) ----------
__device__ int   g_cnt[NN];
__device__ int   g_cursor[NN];
__device__ int   g_rowstart[NN + 1];
__device__ int   g_src[EE];
__device__ float g_dinv[NN];
__device__ __nv_bfloat16 g_h1b[NN * FH];  // lin1 = emb[x] @ W1  (bf16)
__device__ float g_a1[NN * FH];           // relu(gcn1)          (fp32)
__device__ __nv_bfloat16 g_z2b[NN * FO];  // lin2 = a1 @ W2      (bf16)
__device__ __nv_bfloat16 g_zb[NN * FO];   // z (gcn2 out)        (bf16)

// ---------------- CSR build ------------------------------------------------
__global__ void k_init() {
    int i = blockIdx.x * blockDim.x + threadIdx.x;
    if (i < NN) { g_cnt[i] = 0; g_cursor[i] = 0; }
}

__global__ void k_count(const int* __restrict__ dst) {
    int e = blockIdx.x * blockDim.x + threadIdx.x;
    if (e < EE) atomicAdd(&g_cnt[dst[e]], 1);
}

// one block, 1024 threads, 8 elems/thread: scan counts -> rowstart, dinv
__global__ void __launch_bounds__(1024) k_scan() {
    __shared__ int s[1024];
    int t = threadIdx.x;
    int base = t * 8;
    int v[8]; int sum = 0;
#pragma unroll
    for (int i = 0; i < 8; i++) { v[i] = g_cnt[base + i]; sum += v[i]; }
    s[t] = sum;
    __syncthreads();
    for (int off = 1; off < 1024; off <<= 1) {
        int add = (t >= off) ? s[t - off] : 0;
        __syncthreads();
        s[t] += add;
        __syncthreads();
    }
    int run = s[t] - sum;  // exclusive prefix
#pragma unroll
    for (int i = 0; i < 8; i++) {
        g_rowstart[base + i] = run;
        run += v[i];
        g_dinv[base + i] = rsqrtf((float)v[i] + 1.0f);  // +1 self loop
    }
    if (t == 1023) g_rowstart[NN] = run;
}

__global__ void k_fill(const int* __restrict__ src, const int* __restrict__ dst) {
    int e = blockIdx.x * blockDim.x + threadIdx.x;
    if (e < EE) {
        int d = dst[e];
        int p = atomicAdd(&g_cursor[d], 1);
        g_src[g_rowstart[d] + p] = src[e];
    }
}

// ---------------- lin1: g_h1b = emb[x] @ W1  (16 nodes / block) ------------
__global__ void __launch_bounds__(256) k_lin1(const int* __restrict__ x,
                                              const float* __restrict__ emb,
                                              const float* __restrict__ W1) {
    __shared__ float se[16][FIN];
    __shared__ int   sx[16];
    int t = threadIdx.x;
    int n0 = blockIdx.x * 16;
    if (t < 16) sx[t] = x[n0 + t];
    __syncthreads();
    for (int i = t; i < 16 * FIN; i += 256) {
        int r = i >> 7, k = i & 127;
        se[r][k] = emb[sx[r] * FIN + k];
    }
    __syncthreads();
    float acc[16];
#pragma unroll
    for (int r = 0; r < 16; r++) acc[r] = 0.f;
    const float* w = W1 + t;  // column t, coalesced across threads
    for (int k = 0; k < FIN; k++) {
        float wv = w[k * FH];
#pragma unroll
        for (int r = 0; r < 16; r++) acc[r] = fmaf(se[r][k], wv, acc[r]);
    }
#pragma unroll
    for (int r = 0; r < 16; r++)
        g_h1b[(n0 + r) * FH + t] = __float2bfloat16(acc[r]);
}

// ---------------- lin2: g_z2b = a1 @ W2 (16 nodes / block, 128 threads) ----
__global__ void __launch_bounds__(128) k_lin2(const float* __restrict__ W2) {
    __shared__ float sa[16][FH];
    int t = threadIdx.x;
    int n0 = blockIdx.x * 16;
    for (int i = t; i < 16 * FH; i += 128) {
        int r = i >> 8, k = i & 255;
        sa[r][k] = g_a1[(n0 + r) * FH + k];
    }
    __syncthreads();
    float acc[16];
#pragma unroll
    for (int r = 0; r < 16; r++) acc[r] = 0.f;
    for (int k = 0; k < FH; k++) {
        float wv = W2[k * FO + t];
#pragma unroll
        for (int r = 0; r < 16; r++) acc[r] = fmaf(sa[r][k], wv, acc[r]);
    }
#pragma unroll
    for (int r = 0; r < 16; r++)
        g_z2b[(n0 + r) * FO + t] = __float2bfloat16(acc[r]);
}

// ---------------- GCN aggregation, layer 1 (bf16x2 gathers, fp32 accum) ----
__global__ void __launch_bounds__(128) k_agg1(const float* __restrict__ bias) {
    const __nv_bfloat162* __restrict__ H = (const __nv_bfloat162*)g_h1b;
    int d = blockIdx.x;
    int t = threadIdx.x;          // handles features 2t, 2t+1
    int i = g_rowstart[d], end = g_rowstart[d + 1];
    float ax = 0.f, ay = 0.f;
    for (; i + 4 <= end; i += 4) {
        int s0 = g_src[i], s1 = g_src[i + 1], s2 = g_src[i + 2], s3 = g_src[i + 3];
        float w0 = g_dinv[s0], w1 = g_dinv[s1], w2 = g_dinv[s2], w3 = g_dinv[s3];
        float2 f0 = __bfloat1622float2(H[s0 * 128 + t]);
        float2 f1 = __bfloat1622float2(H[s1 * 128 + t]);
        float2 f2 = __bfloat1622float2(H[s2 * 128 + t]);
        float2 f3 = __bfloat1622float2(H[s3 * 128 + t]);
        ax += w0 * f0.x + w1 * f1.x + w2 * f2.x + w3 * f3.x;
        ay += w0 * f0.y + w1 * f1.y + w2 * f2.y + w3 * f3.y;
    }
    for (; i < end; i++) {
        int s0 = g_src[i];
        float w0 = g_dinv[s0];
        float2 f0 = __bfloat1622float2(H[s0 * 128 + t]);
        ax += w0 * f0.x;
        ay += w0 * f0.y;
    }
    float dd = g_dinv[d];
    float2 hs = __bfloat1622float2(H[d * 128 + t]);
    float2 bb = ((const float2*)bias)[t];
    float rx = fmaf(dd, ax, dd * dd * hs.x) + bb.x;
    float ry = fmaf(dd, ay, dd * dd * hs.y) + bb.y;
    ((float2*)g_a1)[d * 128 + t] = make_float2(fmaxf(rx, 0.f), fmaxf(ry, 0.f));
}

// ---------------- GCN aggregation, layer 2 ----------------------------------
__global__ void __launch_bounds__(64) k_agg2(const float* __restrict__ bias) {
    const __nv_bfloat162* __restrict__ Z = (const __nv_bfloat162*)g_z2b;
    int d = blockIdx.x;
    int t = threadIdx.x;          // handles features 2t, 2t+1 (64 threads)
    int i = g_rowstart[d], end = g_rowstart[d + 1];
    float ax = 0.f, ay = 0.f;
    for (; i + 4 <= end; i += 4) {
        int s0 = g_src[i], s1 = g_src[i + 1], s2 = g_src[i + 2], s3 = g_src[i + 3];
        float w0 = g_dinv[s0], w1 = g_dinv[s1], w2 = g_dinv[s2], w3 = g_dinv[s3];
        float2 f0 = __bfloat1622float2(Z[s0 * 64 + t]);
        float2 f1 = __bfloat1622float2(Z[s1 * 64 + t]);
        float2 f2 = __bfloat1622float2(Z[s2 * 64 + t]);
        float2 f3 = __bfloat1622float2(Z[s3 * 64 + t]);
        ax += w0 * f0.x + w1 * f1.x + w2 * f2.x + w3 * f3.x;
        ay += w0 * f0.y + w1 * f1.y + w2 * f2.y + w3 * f3.y;
    }
    for (; i < end; i++) {
        int s0 = g_src[i];
        float w0 = g_dinv[s0];
        float2 f0 = __bfloat1622float2(Z[s0 * 64 + t]);
        ax += w0 * f0.x;
        ay += w0 * f0.y;
    }
    float dd = g_dinv[d];
    float2 zs = __bfloat1622float2(Z[d * 64 + t]);
    float2 bb = ((const float2*)bias)[t];
    float rx = fmaf(dd, ax, dd * dd * zs.x) + bb.x;
    float ry = fmaf(dd, ay, dd * dd * zs.y) + bb.y;
    ((__nv_bfloat162*)g_zb)[d * 64 + t] = __floats2bfloat162_rn(rx, ry);
}

// ---------------- decode: out = sigmoid(z @ z^T), bf16 mma, symmetric ------
// Epilogue uses cp.async.bulk (TMA path) row stores instead of per-thread STG
// (store-issue was the R3 bottleneck).
__device__ __forceinline__ float sigmoidf_(float v) {
    return 1.0f / (1.0f + __expf(-v));
}

__device__ __forceinline__ uint32_t smem_u32(const void* p) {
    return (uint32_t)__cvta_generic_to_shared(p);
}

__device__ __forceinline__ void bulk_store_row(void* gptr, uint32_t saddr, int bytes) {
    asm volatile("cp.async.bulk.global.shared::cta.bulk_group [%0], [%1], %2;"
                 :: "l"(gptr), "r"(saddr), "r"(bytes) : "memory");
}

__global__ void __launch_bounds__(256) k_decode(float* __restrict__ out) {
    int bi = blockIdx.y, bj = blockIdx.x;
    if (bj < bi) return;

    constexpr int P  = 136;  // bf16 pitch for MMA tiles
    constexpr int PF = 136;  // fp32 pitch for output staging (128*136*4 = 69632)
    extern __shared__ __nv_bfloat16 sm[];
    __nv_bfloat16* sA = sm;
    __nv_bfloat16* sB = sm + 128 * P;
    float* sf = (float*)sm;  // reused after MMA

    int t  = threadIdx.x;
    int i0 = bi * 128;
    int j0 = bj * 128;

    // cooperative load: 2 tiles x 128 rows x 16 uint4
    for (int v = t; v < 4096; v += 256) {
        int which = v >> 11;               // 0 = A, 1 = B
        int r = (v >> 4) & 127;
        int c = (v & 15) * 8;
        const __nv_bfloat16* srcp = g_zb + (size_t)((which ? j0 : i0) + r) * FO + c;
        __nv_bfloat16* dstp = (which ? sB : sA) + r * P + c;
        *(uint4*)dstp = *(const uint4*)srcp;
    }
    __syncthreads();

    int lane = t & 31, w = t >> 5;
    int wm = (w & 3) * 32;   // warp row offset within tile
    int wn = (w >> 2) * 64;  // warp col offset within tile

    float acc[2][8][4];
#pragma unroll
    for (int mt = 0; mt < 2; mt++)
#pragma unroll
        for (int nt = 0; nt < 8; nt++)
#pragma unroll
            for (int q = 0; q < 4; q++) acc[mt][nt][q] = 0.f;

#pragma unroll
    for (int ks = 0; ks < 8; ks++) {
        int k0 = ks * 16;
        uint32_t a[2][4];
#pragma unroll
        for (int mt = 0; mt < 2; mt++) {
            const __nv_bfloat16* p = sA + (wm + mt * 16 + (lane & 15)) * P
                                        + k0 + (lane >> 4) * 8;
            uint32_t addr = smem_u32(p);
            asm volatile("ldmatrix.sync.aligned.m8n8.x4.shared.b16 {%0,%1,%2,%3}, [%4];"
                         : "=r"(a[mt][0]), "=r"(a[mt][1]), "=r"(a[mt][2]), "=r"(a[mt][3])
                         : "r"(addr));
        }
        uint32_t b[8][2];
#pragma unroll
        for (int pr = 0; pr < 4; pr++) {
            const __nv_bfloat16* p = sB + (wn + pr * 16 + (lane >> 4) * 8 + (lane & 7)) * P
                                        + k0 + ((lane >> 3) & 1) * 8;
            uint32_t addr = smem_u32(p);
            asm volatile("ldmatrix.sync.aligned.m8n8.x4.shared.b16 {%0,%1,%2,%3}, [%4];"
                         : "=r"(b[2 * pr][0]), "=r"(b[2 * pr][1]),
                           "=r"(b[2 * pr + 1][0]), "=r"(b[2 * pr + 1][1])
                         : "r"(addr));
        }
#pragma unroll
        for (int mt = 0; mt < 2; mt++)
#pragma unroll
            for (int nt = 0; nt < 8; nt++)
                asm volatile(
                    "mma.sync.aligned.m16n8k16.row.col.f32.bf16.bf16.f32 "
                    "{%0,%1,%2,%3}, {%4,%5,%6,%7}, {%8,%9}, {%0,%1,%2,%3};"
                    : "+f"(acc[mt][nt][0]), "+f"(acc[mt][nt][1]),
                      "+f"(acc[mt][nt][2]), "+f"(acc[mt][nt][3])
                    : "r"(a[mt][0]), "r"(a[mt][1]), "r"(a[mt][2]), "r"(a[mt][3]),
                      "r"(b[nt][0]), "r"(b[nt][1]));
    }

    // sigmoid once, in place (values reused by both store passes)
#pragma unroll
    for (int mt = 0; mt < 2; mt++)
#pragma unroll
        for (int nt = 0; nt < 8; nt++)
#pragma unroll
            for (int q = 0; q < 4; q++) acc[mt][nt][q] = sigmoidf_(acc[mt][nt][q]);

    bool diag = (bi == bj);
    __syncthreads();  // all warps done reading sA/sB before staging reuses it

    // ---- pass 1: direct tile, row-major staging, bulk-store 128 rows ----
    int r0b = wm + (lane >> 2);
#pragma unroll
    for (int mt = 0; mt < 2; mt++) {
        int r0 = r0b + mt * 16;
#pragma unroll
        for (int nt = 0; nt < 8; nt++) {
            int c0 = wn + nt * 8 + (lane & 3) * 2;
            *(float2*)&sf[r0 * PF + c0]       = make_float2(acc[mt][nt][0], acc[mt][nt][1]);
            *(float2*)&sf[(r0 + 8) * PF + c0] = make_float2(acc[mt][nt][2], acc[mt][nt][3]);
        }
    }
    __syncthreads();
    if (t < 128) {
        asm volatile("fence.proxy.async.shared::cta;" ::: "memory");
        bulk_store_row(out + (size_t)(i0 + t) * NN + j0, smem_u32(&sf[t * PF]), 512);
        asm volatile("cp.async.bulk.commit_group;" ::: "memory");
        asm volatile("cp.async.bulk.wait_group.read 0;" ::: "memory");
    }
    __syncthreads();

    // ---- pass 2: mirror tile (transposed), bulk-store 128 rows ----
    if (!diag) {
#pragma unroll
        for (int mt = 0; mt < 2; mt++) {
            int r0 = r0b + mt * 16;
#pragma unroll
            for (int nt = 0; nt < 8; nt++) {
                int c0 = wn + nt * 8 + (lane & 3) * 2;
                sf[c0 * PF + r0]           = acc[mt][nt][0];
                sf[(c0 + 1) * PF + r0]     = acc[mt][nt][1];
                sf[c0 * PF + r0 + 8]       = acc[mt][nt][2];
                sf[(c0 + 1) * PF + r0 + 8] = acc[mt][nt][3];
            }
        }
        __syncthreads();
        if (t < 128) {
            asm volatile("fence.proxy.async.shared::cta;" ::: "memory");
            bulk_store_row(out + (size_t)(j0 + t) * NN + i0, smem_u32(&sf[t * PF]), 512);
            asm volatile("cp.async.bulk.commit_group;" ::: "memory");
            asm volatile("cp.async.bulk.wait_group.read 0;" ::: "memory");
        }
        __syncthreads();
    }
}

// ---------------- launch ----------------------------------------------------
extern "C" void kernel_launch(void* const* d_in, const int* in_sizes, int n_in,
                              void* d_out, int out_size) {
    const int*   x   = (const int*)d_in[0];
    const int*   ei  = (const int*)d_in[1];   // [2, E]: src then dst
    const float* emb = (const float*)d_in[2];
    const float* W1  = (const float*)d_in[3];
    const float* b1  = (const float*)d_in[4];
    const float* W2  = (const float*)d_in[5];
    const float* b2  = (const float*)d_in[6];
    float* out = (float*)d_out;

    const int* src = ei;
    const int* dst = ei + EE;

    const int smem = 128 * 136 * (int)sizeof(float);  // 69632
    cudaFuncSetAttribute(k_decode, cudaFuncAttributeMaxDynamicSharedMemorySize, smem);

    k_init <<<NN / 256, 256>>>();
    k_count<<<EE / 256, 256>>>(dst);
    k_scan <<<1, 1024>>>();
    k_fill <<<EE / 256, 256>>>(src, dst);

    k_lin1<<<NN / 16, 256>>>(x, emb, W1);
    k_agg1<<<NN, 128>>>(b1);
    k_lin2<<<NN / 16, 128>>>(W2);
    k_agg2<<<NN, 64>>>(b2);

    dim3 grid(NN / 128, NN / 128);
    k_decode<<<grid, 256, smem>>>(out);
}

// round 5
// speedup vs baseline: 1.5183x; 1.2433x over previous
#include <cuda_runtime.h>
#include <cuda_bf16.h>
#include <cstdint>

static constexpr int NN  = 8192;
static constexpr int EE  = 524288;
static constexpr int FIN = 128;
static constexpr int FH  = 256;
static constexpr int FO  = 128;

// ---------------- scratch (device globals; no allocation allowed) ----------
__device__ int   g_cnt[NN];        // zeroed by k_scan each run (BSS-zero at load)
__device__ int   g_cursor[NN];     // set to rowstart by k_scan each run
__device__ int   g_rowstart[NN + 1];
__device__ int   g_src[EE];
__device__ float g_dinv[NN];
__device__ __nv_bfloat16 g_w1t[FH * FIN];   // W1^T bf16  [256][128]
__device__ __nv_bfloat16 g_w2t[FO * FH];    // W2^T bf16  [128][256]
__device__ __nv_bfloat16 g_h1b[NN * FH];    // lin1 out   (bf16)
__device__ __nv_bfloat16 g_a1b[NN * FH];    // relu(gcn1) (bf16)
__device__ __nv_bfloat16 g_z2b[NN * FO];    // lin2 out   (bf16)
__device__ __nv_bfloat16 g_zb[NN * FO];     // z (gcn2)   (bf16)

// ---------------- weight prep: transpose + bf16 ----------------------------
__global__ void k_wconv(const float* __restrict__ W1, const float* __restrict__ W2) {
    int idx = blockIdx.x * blockDim.x + threadIdx.x;   // 65536 threads
    if (idx < FH * FIN) {
        int j = idx >> 7, k = idx & 127;               // w1t[j][k] = W1[k][j]
        g_w1t[idx] = __float2bfloat16(W1[k * FH + j]);
    } else {
        int i2 = idx - FH * FIN;
        int j = i2 >> 8, k = i2 & 255;                 // w2t[j][k] = W2[k][j]
        g_w2t[i2] = __float2bfloat16(W2[k * FO + j]);
    }
}

// ---------------- CSR build ------------------------------------------------
__global__ void k_count(const int* __restrict__ dst) {
    int e = blockIdx.x * blockDim.x + threadIdx.x;
    if (e < EE) atomicAdd(&g_cnt[dst[e]], 1);
}

// one block, 1024 threads, 8 elems/thread: scan counts -> rowstart, cursor,
// dinv; re-zeroes g_cnt for the next replay.
__global__ void __launch_bounds__(1024) k_scan() {
    __shared__ int s[1024];
    int t = threadIdx.x;
    int base = t * 8;
    int v[8]; int sum = 0;
#pragma unroll
    for (int i = 0; i < 8; i++) { v[i] = g_cnt[base + i]; sum += v[i]; }
#pragma unroll
    for (int i = 0; i < 8; i++) g_cnt[base + i] = 0;   // reset for next replay
    s[t] = sum;
    __syncthreads();
    for (int off = 1; off < 1024; off <<= 1) {
        int add = (t >= off) ? s[t - off] : 0;
        __syncthreads();
        s[t] += add;
        __syncthreads();
    }
    int run = s[t] - sum;  // exclusive prefix
#pragma unroll
    for (int i = 0; i < 8; i++) {
        g_rowstart[base + i] = run;
        g_cursor[base + i]   = run;                    // fill scatters from here
        run += v[i];
        g_dinv[base + i] = rsqrtf((float)v[i] + 1.0f); // +1 self loop
    }
    if (t == 1023) g_rowstart[NN] = run;
}

__global__ void k_fill(const int* __restrict__ src, const int* __restrict__ dst) {
    int e = blockIdx.x * blockDim.x + threadIdx.x;
    if (e < EE) {
        int p = atomicAdd(&g_cursor[dst[e]], 1);
        g_src[p] = src[e];
    }
}

// ---------------- shared mma helpers ----------------------------------------
__device__ __forceinline__ uint32_t smem_u32(const void* p) {
    return (uint32_t)__cvta_generic_to_shared(p);
}

__device__ __forceinline__ void ldmat4(uint32_t* r, const __nv_bfloat16* p) {
    asm volatile("ldmatrix.sync.aligned.m8n8.x4.shared.b16 {%0,%1,%2,%3}, [%4];"
                 : "=r"(r[0]), "=r"(r[1]), "=r"(r[2]), "=r"(r[3])
                 : "r"(smem_u32(p)));
}

__device__ __forceinline__ void mma16816(float* c, const uint32_t* a, const uint32_t* b) {
    asm volatile("mma.sync.aligned.m16n8k16.row.col.f32.bf16.bf16.f32 "
                 "{%0,%1,%2,%3}, {%4,%5,%6,%7}, {%8,%9}, {%0,%1,%2,%3};"
                 : "+f"(c[0]), "+f"(c[1]), "+f"(c[2]), "+f"(c[3])
                 : "r"(a[0]), "r"(a[1]), "r"(a[2]), "r"(a[3]), "r"(b[0]), "r"(b[1]));
}

// ---------------- lin1: g_h1b = bf16( emb[x] @ W1 ), tensor cores ----------
// block tile 64 nodes x 256 cols, K=128; 8 warps, warp tile 32x64.
__global__ void __launch_bounds__(256) k_lin1(const int* __restrict__ x,
                                              const float* __restrict__ emb) {
    constexpr int P = 136;
    extern __shared__ __nv_bfloat16 sm1[];
    __nv_bfloat16* sA = sm1;              // 64  x P
    __nv_bfloat16* sB = sm1 + 64 * P;     // 256 x P
    __shared__ int sx[64];

    int t = threadIdx.x;
    int n0 = blockIdx.x * 64;
    if (t < 64) sx[t] = x[n0 + t];
    __syncthreads();

    for (int v = t; v < 2048; v += 256) {       // A: 64 rows x 32 float4
        int r = v >> 5, m = v & 31;
        float4 f = *(const float4*)(emb + (size_t)sx[r] * FIN + m * 4);
        uint32_t p0 = __float_as_uint(0), p1 = 0;
        __nv_bfloat162 b0 = __floats2bfloat162_rn(f.x, f.y);
        __nv_bfloat162 b1 = __floats2bfloat162_rn(f.z, f.w);
        p0 = *(uint32_t*)&b0; p1 = *(uint32_t*)&b1;
        *(uint2*)&sA[r * P + m * 4] = make_uint2(p0, p1);
    }
    for (int v = t; v < 4096; v += 256) {       // B: w1t 256 rows x 16 uint4
        int r = v >> 4, m = v & 15;
        *(uint4*)&sB[r * P + m * 8] = ((const uint4*)g_w1t)[v];
    }
    __syncthreads();

    int lane = t & 31, w = t >> 5;
    int wm = (w & 1) * 32, wn = (w >> 1) * 64;

    float acc[2][8][4] = {};
#pragma unroll
    for (int ks = 0; ks < 8; ks++) {
        int k0 = ks * 16;
        uint32_t a[2][4], b[8][2];
#pragma unroll
        for (int mt = 0; mt < 2; mt++)
            ldmat4(a[mt], sA + (wm + mt * 16 + (lane & 15)) * P + k0 + (lane >> 4) * 8);
#pragma unroll
        for (int pr = 0; pr < 4; pr++) {
            uint32_t r4[4];
            ldmat4(r4, sB + (wn + pr * 16 + (lane >> 4) * 8 + (lane & 7)) * P
                         + k0 + ((lane >> 3) & 1) * 8);
            b[2 * pr][0] = r4[0]; b[2 * pr][1] = r4[1];
            b[2 * pr + 1][0] = r4[2]; b[2 * pr + 1][1] = r4[3];
        }
#pragma unroll
        for (int mt = 0; mt < 2; mt++)
#pragma unroll
            for (int nt = 0; nt < 8; nt++) mma16816(acc[mt][nt], a[mt], b[nt]);
    }

#pragma unroll
    for (int mt = 0; mt < 2; mt++) {
        int row = wm + mt * 16 + (lane >> 2);
#pragma unroll
        for (int nt = 0; nt < 8; nt++) {
            int col = wn + nt * 8 + (lane & 3) * 2;
            *(__nv_bfloat162*)&g_h1b[(size_t)(n0 + row) * FH + col] =
                __floats2bfloat162_rn(acc[mt][nt][0], acc[mt][nt][1]);
            *(__nv_bfloat162*)&g_h1b[(size_t)(n0 + row + 8) * FH + col] =
                __floats2bfloat162_rn(acc[mt][nt][2], acc[mt][nt][3]);
        }
    }
}

// ---------------- lin2: g_z2b = bf16( a1 @ W2 ), tensor cores --------------
// block tile 64 nodes x 128 cols, K=256; 8 warps, warp tile 32x32.
__global__ void __launch_bounds__(256) k_lin2() {
    constexpr int P = 264;
    extern __shared__ __nv_bfloat16 sm2[];
    __nv_bfloat16* sA = sm2;              // 64  x P
    __nv_bfloat16* sB = sm2 + 64 * P;     // 128 x P

    int t = threadIdx.x;
    int n0 = blockIdx.x * 64;

    for (int v = t; v < 2048; v += 256) {       // A: 64 rows x 32 uint4
        int r = v >> 5, m = v & 31;
        *(uint4*)&sA[r * P + m * 8] =
            *(const uint4*)&g_a1b[(size_t)(n0 + r) * FH + m * 8];
    }
    for (int v = t; v < 4096; v += 256) {       // B: w2t 128 rows x 32 uint4
        int r = v >> 5, m = v & 31;
        *(uint4*)&sB[r * P + m * 8] = ((const uint4*)g_w2t)[v];
    }
    __syncthreads();

    int lane = t & 31, w = t >> 5;
    int wm = (w & 1) * 32, wn = (w >> 1) * 32;

    float acc[2][4][4] = {};
#pragma unroll
    for (int ks = 0; ks < 16; ks++) {
        int k0 = ks * 16;
        uint32_t a[2][4], b[4][2];
#pragma unroll
        for (int mt = 0; mt < 2; mt++)
            ldmat4(a[mt], sA + (wm + mt * 16 + (lane & 15)) * P + k0 + (lane >> 4) * 8);
#pragma unroll
        for (int pr = 0; pr < 2; pr++) {
            uint32_t r4[4];
            ldmat4(r4, sB + (wn + pr * 16 + (lane >> 4) * 8 + (lane & 7)) * P
                         + k0 + ((lane >> 3) & 1) * 8);
            b[2 * pr][0] = r4[0]; b[2 * pr][1] = r4[1];
            b[2 * pr + 1][0] = r4[2]; b[2 * pr + 1][1] = r4[3];
        }
#pragma unroll
        for (int mt = 0; mt < 2; mt++)
#pragma unroll
            for (int nt = 0; nt < 4; nt++) mma16816(acc[mt][nt], a[mt], b[nt]);
    }

#pragma unroll
    for (int mt = 0; mt < 2; mt++) {
        int row = wm + mt * 16 + (lane >> 2);
#pragma unroll
        for (int nt = 0; nt < 4; nt++) {
            int col = wn + nt * 8 + (lane & 3) * 2;
            *(__nv_bfloat162*)&g_z2b[(size_t)(n0 + row) * FO + col] =
                __floats2bfloat162_rn(acc[mt][nt][0], acc[mt][nt][1]);
            *(__nv_bfloat162*)&g_z2b[(size_t)(n0 + row + 8) * FO + col] =
                __floats2bfloat162_rn(acc[mt][nt][2], acc[mt][nt][3]);
        }
    }
}

// ---------------- GCN aggregation, layer 1 (bf16x2 gathers, fp32 accum) ----
__global__ void __launch_bounds__(128) k_agg1(const float* __restrict__ bias) {
    const __nv_bfloat162* __restrict__ H = (const __nv_bfloat162*)g_h1b;
    int d = blockIdx.x;
    int t = threadIdx.x;          // handles features 2t, 2t+1
    int i = g_rowstart[d], end = g_rowstart[d + 1];
    float ax = 0.f, ay = 0.f;
    for (; i + 4 <= end; i += 4) {
        int s0 = g_src[i], s1 = g_src[i + 1], s2 = g_src[i + 2], s3 = g_src[i + 3];
        float w0 = g_dinv[s0], w1 = g_dinv[s1], w2 = g_dinv[s2], w3 = g_dinv[s3];
        float2 f0 = __bfloat1622float2(H[s0 * 128 + t]);
        float2 f1 = __bfloat1622float2(H[s1 * 128 + t]);
        float2 f2 = __bfloat1622float2(H[s2 * 128 + t]);
        float2 f3 = __bfloat1622float2(H[s3 * 128 + t]);
        ax += w0 * f0.x + w1 * f1.x + w2 * f2.x + w3 * f3.x;
        ay += w0 * f0.y + w1 * f1.y + w2 * f2.y + w3 * f3.y;
    }
    for (; i < end; i++) {
        int s0 = g_src[i];
        float w0 = g_dinv[s0];
        float2 f0 = __bfloat1622float2(H[s0 * 128 + t]);
        ax += w0 * f0.x;
        ay += w0 * f0.y;
    }
    float dd = g_dinv[d];
    float2 hs = __bfloat1622float2(H[d * 128 + t]);
    float2 bb = ((const float2*)bias)[t];
    float rx = fmaf(dd, ax, dd * dd * hs.x) + bb.x;
    float ry = fmaf(dd, ay, dd * dd * hs.y) + bb.y;
    ((__nv_bfloat162*)g_a1b)[d * 128 + t] =
        __floats2bfloat162_rn(fmaxf(rx, 0.f), fmaxf(ry, 0.f));
}

// ---------------- GCN aggregation, layer 2 ----------------------------------
__global__ void __launch_bounds__(64) k_agg2(const float* __restrict__ bias) {
    const __nv_bfloat162* __restrict__ Z = (const __nv_bfloat162*)g_z2b;
    int d = blockIdx.x;
    int t = threadIdx.x;          // handles features 2t, 2t+1 (64 threads)
    int i = g_rowstart[d], end = g_rowstart[d + 1];
    float ax = 0.f, ay = 0.f;
    for (; i + 4 <= end; i += 4) {
        int s0 = g_src[i], s1 = g_src[i + 1], s2 = g_src[i + 2], s3 = g_src[i + 3];
        float w0 = g_dinv[s0], w1 = g_dinv[s1], w2 = g_dinv[s2], w3 = g_dinv[s3];
        float2 f0 = __bfloat1622float2(Z[s0 * 64 + t]);
        float2 f1 = __bfloat1622float2(Z[s1 * 64 + t]);
        float2 f2 = __bfloat1622float2(Z[s2 * 64 + t]);
        float2 f3 = __bfloat1622float2(Z[s3 * 64 + t]);
        ax += w0 * f0.x + w1 * f1.x + w2 * f2.x + w3 * f3.x;
        ay += w0 * f0.y + w1 * f1.y + w2 * f2.y + w3 * f3.y;
    }
    for (; i < end; i++) {
        int s0 = g_src[i];
        float w0 = g_dinv[s0];
        float2 f0 = __bfloat1622float2(Z[s0 * 64 + t]);
        ax += w0 * f0.x;
        ay += w0 * f0.y;
    }
    float dd = g_dinv[d];
    float2 zs = __bfloat1622float2(Z[d * 64 + t]);
    float2 bb = ((const float2*)bias)[t];
    float rx = fmaf(dd, ax, dd * dd * zs.x) + bb.x;
    float ry = fmaf(dd, ay, dd * dd * zs.y) + bb.y;
    ((__nv_bfloat162*)g_zb)[d * 64 + t] = __floats2bfloat162_rn(rx, ry);
}

// ---------------- decode: out = sigmoid(z @ z^T), bf16 mma, symmetric ------
__device__ __forceinline__ float sigmoidf_(float v) {
    return 1.0f / (1.0f + __expf(-v));
}

__device__ __forceinline__ void bulk_store_row(void* gptr, uint32_t saddr, int bytes) {
    asm volatile("cp.async.bulk.global.shared::cta.bulk_group [%0], [%1], %2;"
                 :: "l"(gptr), "r"(saddr), "r"(bytes) : "memory");
}

__global__ void __launch_bounds__(256, 2) k_decode(float* __restrict__ out) {
    int bi = blockIdx.y, bj = blockIdx.x;
    if (bj < bi) return;

    constexpr int P  = 136;  // bf16 pitch for MMA tiles
    constexpr int PF = 136;  // fp32 pitch for output staging (128*136*4 = 69632)
    extern __shared__ __nv_bfloat16 sm[];
    __nv_bfloat16* sA = sm;
    __nv_bfloat16* sB = sm + 128 * P;
    float* sf = (float*)sm;  // reused after MMA

    int t  = threadIdx.x;
    int i0 = bi * 128;
    int j0 = bj * 128;

    for (int v = t; v < 4096; v += 256) {
        int which = v >> 11;               // 0 = A, 1 = B
        int r = (v >> 4) & 127;
        int c = (v & 15) * 8;
        const __nv_bfloat16* srcp = g_zb + (size_t)((which ? j0 : i0) + r) * FO + c;
        __nv_bfloat16* dstp = (which ? sB : sA) + r * P + c;
        *(uint4*)dstp = *(const uint4*)srcp;
    }
    __syncthreads();

    int lane = t & 31, w = t >> 5;
    int wm = (w & 3) * 32;
    int wn = (w >> 2) * 64;

    float acc[2][8][4] = {};
#pragma unroll
    for (int ks = 0; ks < 8; ks++) {
        int k0 = ks * 16;
        uint32_t a[2][4], b[8][2];
#pragma unroll
        for (int mt = 0; mt < 2; mt++)
            ldmat4(a[mt], sA + (wm + mt * 16 + (lane & 15)) * P + k0 + (lane >> 4) * 8);
#pragma unroll
        for (int pr = 0; pr < 4; pr++) {
            uint32_t r4[4];
            ldmat4(r4, sB + (wn + pr * 16 + (lane >> 4) * 8 + (lane & 7)) * P
                         + k0 + ((lane >> 3) & 1) * 8);
            b[2 * pr][0] = r4[0]; b[2 * pr][1] = r4[1];
            b[2 * pr + 1][0] = r4[2]; b[2 * pr + 1][1] = r4[3];
        }
#pragma unroll
        for (int mt = 0; mt < 2; mt++)
#pragma unroll
            for (int nt = 0; nt < 8; nt++) mma16816(acc[mt][nt], a[mt], b[nt]);
    }

#pragma unroll
    for (int mt = 0; mt < 2; mt++)
#pragma unroll
        for (int nt = 0; nt < 8; nt++)
#pragma unroll
            for (int q = 0; q < 4; q++) acc[mt][nt][q] = sigmoidf_(acc[mt][nt][q]);

    bool diag = (bi == bj);
    __syncthreads();  // all warps done reading sA/sB before staging reuses it

    // pass 1: direct tile, row-major staging, bulk-store 128 rows
    int r0b = wm + (lane >> 2);
#pragma unroll
    for (int mt = 0; mt < 2; mt++) {
        int r0 = r0b + mt * 16;
#pragma unroll
        for (int nt = 0; nt < 8; nt++) {
            int c0 = wn + nt * 8 + (lane & 3) * 2;
            *(float2*)&sf[r0 * PF + c0]       = make_float2(acc[mt][nt][0], acc[mt][nt][1]);
            *(float2*)&sf[(r0 + 8) * PF + c0] = make_float2(acc[mt][nt][2], acc[mt][nt][3]);
        }
    }
    __syncthreads();
    if (t < 128) {
        asm volatile("fence.proxy.async.shared::cta;" ::: "memory");
        bulk_store_row(out + (size_t)(i0 + t) * NN + j0, smem_u32(&sf[t * PF]), 512);
        asm volatile("cp.async.bulk.commit_group;" ::: "memory");
        asm volatile("cp.async.bulk.wait_group.read 0;" ::: "memory");
    }
    __syncthreads();

    // pass 2: mirror tile (transposed), bulk-store 128 rows
    if (!diag) {
#pragma unroll
        for (int mt = 0; mt < 2; mt++) {
            int r0 = r0b + mt * 16;
#pragma unroll
            for (int nt = 0; nt < 8; nt++) {
                int c0 = wn + nt * 8 + (lane & 3) * 2;
                sf[c0 * PF + r0]           = acc[mt][nt][0];
                sf[(c0 + 1) * PF + r0]     = acc[mt][nt][1];
                sf[c0 * PF + r0 + 8]       = acc[mt][nt][2];
                sf[(c0 + 1) * PF + r0 + 8] = acc[mt][nt][3];
            }
        }
        __syncthreads();
        if (t < 128) {
            asm volatile("fence.proxy.async.shared::cta;" ::: "memory");
            bulk_store_row(out + (size_t)(j0 + t) * NN + i0, smem_u32(&sf[t * PF]), 512);
            asm volatile("cp.async.bulk.commit_group;" ::: "memory");
            asm volatile("cp.async.bulk.wait_group.read 0;" ::: "memory");
        }
        __syncthreads();
    }
}

// ---------------- launch ----------------------------------------------------
extern "C" void kernel_launch(void* const* d_in, const int* in_sizes, int n_in,
                              void* d_out, int out_size) {
    const int*   x   = (const int*)d_in[0];
    const int*   ei  = (const int*)d_in[1];   // [2, E]: src then dst
    const float* emb = (const float*)d_in[2];
    const float* W1  = (const float*)d_in[3];
    const float* b1  = (const float*)d_in[4];
    const float* W2  = (const float*)d_in[5];
    const float* b2  = (const float*)d_in[6];
    float* out = (float*)d_out;

    const int* src = ei;
    const int* dst = ei + EE;

    const int smem_dec  = 128 * 136 * (int)sizeof(float);              // 69632
    const int smem_lin1 = (64 + 256) * 136 * (int)sizeof(__nv_bfloat16); // 87040
    const int smem_lin2 = (64 + 128) * 264 * (int)sizeof(__nv_bfloat16); // 101376
    cudaFuncSetAttribute(k_decode, cudaFuncAttributeMaxDynamicSharedMemorySize, smem_dec);
    cudaFuncSetAttribute(k_lin1,   cudaFuncAttributeMaxDynamicSharedMemorySize, smem_lin1);
    cudaFuncSetAttribute(k_lin2,   cudaFuncAttributeMaxDynamicSharedMemorySize, smem_lin2);

    k_wconv<<<256, 256>>>(W1, W2);
    k_count<<<EE / 256, 256>>>(dst);
    k_scan <<<1, 1024>>>();
    k_fill <<<EE / 256, 256>>>(src, dst);

    k_lin1<<<NN / 64, 256, smem_lin1>>>(x, emb);
    k_agg1<<<NN, 128>>>(b1);
    k_lin2<<<NN / 64, 256, smem_lin2>>>();
    k_agg2<<<NN, 64>>>(b2);

    dim3 grid(NN / 128, NN / 128);
    k_decode<<<grid, 256, smem_dec>>>(out);
}

// round 6
// speedup vs baseline: 1.7082x; 1.1251x over previous
#include <cuda_runtime.h>
#include <cuda_bf16.h>
#include <cstdint>

static constexpr int NN  = 8192;
static constexpr int EE  = 524288;
static constexpr int FIN = 128;
static constexpr int FH  = 256;
static constexpr int FO  = 128;

// ---------------- scratch (device globals; no allocation allowed) ----------
__device__ int   g_cnt[NN];        // zeroed by k_scan each run (BSS-zero at load)
__device__ int   g_cursor[NN];     // set to rowstart by k_scan each run
__device__ int   g_rowstart[NN + 1];
__device__ int   g_src[EE];
__device__ float g_dinv[NN];
__device__ __nv_bfloat16 g_w1t[FH * FIN];   // W1^T bf16  [256][128]
__device__ __nv_bfloat16 g_w2t[FO * FH];    // W2^T bf16  [128][256]
__device__ __nv_bfloat16 g_h1b[NN * FH];    // lin1 out   (bf16)
__device__ __nv_bfloat16 g_a1b[NN * FH];    // relu(gcn1) (bf16)
__device__ __nv_bfloat16 g_z2b[NN * FO];    // lin2 out   (bf16)
__device__ __nv_bfloat16 g_zb[NN * FO];     // z (gcn2)   (bf16)

// ---------------- weight prep: transpose + bf16 ----------------------------
__global__ void k_wconv(const float* __restrict__ W1, const float* __restrict__ W2) {
    int idx = blockIdx.x * blockDim.x + threadIdx.x;   // 65536 threads
    if (idx < FH * FIN) {
        int j = idx >> 7, k = idx & 127;               // w1t[j][k] = W1[k][j]
        g_w1t[idx] = __float2bfloat16(W1[k * FH + j]);
    } else {
        int i2 = idx - FH * FIN;
        int j = i2 >> 8, k = i2 & 255;                 // w2t[j][k] = W2[k][j]
        g_w2t[i2] = __float2bfloat16(W2[k * FO + j]);
    }
}

// ---------------- CSR build ------------------------------------------------
// 4 edges per thread: 4 independent atomic chains hide ATOMG latency.
__global__ void k_count(const int* __restrict__ dst) {
    int e = (blockIdx.x * blockDim.x + threadIdx.x) * 4;
    int4 d = *(const int4*)(dst + e);
    atomicAdd(&g_cnt[d.x], 1);
    atomicAdd(&g_cnt[d.y], 1);
    atomicAdd(&g_cnt[d.z], 1);
    atomicAdd(&g_cnt[d.w], 1);
}

// one block, 1024 threads, 8 elems/thread: scan counts -> rowstart, cursor,
// dinv; re-zeroes g_cnt for the next replay.
__global__ void __launch_bounds__(1024) k_scan() {
    __shared__ int s[1024];
    int t = threadIdx.x;
    int base = t * 8;
    int v[8]; int sum = 0;
#pragma unroll
    for (int i = 0; i < 8; i++) { v[i] = g_cnt[base + i]; sum += v[i]; }
#pragma unroll
    for (int i = 0; i < 8; i++) g_cnt[base + i] = 0;   // reset for next replay
    s[t] = sum;
    __syncthreads();
    for (int off = 1; off < 1024; off <<= 1) {
        int add = (t >= off) ? s[t - off] : 0;
        __syncthreads();
        s[t] += add;
        __syncthreads();
    }
    int run = s[t] - sum;  // exclusive prefix
#pragma unroll
    for (int i = 0; i < 8; i++) {
        g_rowstart[base + i] = run;
        g_cursor[base + i]   = run;                    // fill scatters from here
        run += v[i];
        g_dinv[base + i] = rsqrtf((float)v[i] + 1.0f); // +1 self loop
    }
    if (t == 1023) g_rowstart[NN] = run;
}

__global__ void k_fill(const int* __restrict__ src, const int* __restrict__ dst) {
    int e = (blockIdx.x * blockDim.x + threadIdx.x) * 4;
    int4 d = *(const int4*)(dst + e);
    int4 s = *(const int4*)(src + e);
    int p0 = atomicAdd(&g_cursor[d.x], 1);
    int p1 = atomicAdd(&g_cursor[d.y], 1);
    int p2 = atomicAdd(&g_cursor[d.z], 1);
    int p3 = atomicAdd(&g_cursor[d.w], 1);
    g_src[p0] = s.x;
    g_src[p1] = s.y;
    g_src[p2] = s.z;
    g_src[p3] = s.w;
}

// ---------------- shared mma helpers ----------------------------------------
__device__ __forceinline__ uint32_t smem_u32(const void* p) {
    return (uint32_t)__cvta_generic_to_shared(p);
}

__device__ __forceinline__ void ldmat4(uint32_t* r, const __nv_bfloat16* p) {
    asm volatile("ldmatrix.sync.aligned.m8n8.x4.shared.b16 {%0,%1,%2,%3}, [%4];"
                 : "=r"(r[0]), "=r"(r[1]), "=r"(r[2]), "=r"(r[3])
                 : "r"(smem_u32(p)));
}

__device__ __forceinline__ void mma16816(float* c, const uint32_t* a, const uint32_t* b) {
    asm volatile("mma.sync.aligned.m16n8k16.row.col.f32.bf16.bf16.f32 "
                 "{%0,%1,%2,%3}, {%4,%5,%6,%7}, {%8,%9}, {%0,%1,%2,%3};"
                 : "+f"(c[0]), "+f"(c[1]), "+f"(c[2]), "+f"(c[3])
                 : "r"(a[0]), "r"(a[1]), "r"(a[2]), "r"(a[3]), "r"(b[0]), "r"(b[1]));
}

// ---------------- lin1: g_h1b = bf16( emb[x] @ W1 ), tensor cores ----------
// block tile 64 nodes x 256 cols, K=128; 8 warps, warp tile 32x64.
__global__ void __launch_bounds__(256) k_lin1(const int* __restrict__ x,
                                              const float* __restrict__ emb) {
    constexpr int P = 136;
    extern __shared__ __nv_bfloat16 sm1[];
    __nv_bfloat16* sA = sm1;              // 64  x P
    __nv_bfloat16* sB = sm1 + 64 * P;     // 256 x P
    __shared__ int sx[64];

    int t = threadIdx.x;
    int n0 = blockIdx.x * 64;
    if (t < 64) sx[t] = x[n0 + t];
    __syncthreads();

    for (int v = t; v < 2048; v += 256) {       // A: 64 rows x 32 float4
        int r = v >> 5, m = v & 31;
        float4 f = *(const float4*)(emb + (size_t)sx[r] * FIN + m * 4);
        __nv_bfloat162 b0 = __floats2bfloat162_rn(f.x, f.y);
        __nv_bfloat162 b1 = __floats2bfloat162_rn(f.z, f.w);
        *(uint2*)&sA[r * P + m * 4] = make_uint2(*(uint32_t*)&b0, *(uint32_t*)&b1);
    }
    for (int v = t; v < 4096; v += 256) {       // B: w1t 256 rows x 16 uint4
        int r = v >> 4, m = v & 15;
        *(uint4*)&sB[r * P + m * 8] = ((const uint4*)g_w1t)[v];
    }
    __syncthreads();

    int lane = t & 31, w = t >> 5;
    int wm = (w & 1) * 32, wn = (w >> 1) * 64;

    float acc[2][8][4] = {};
#pragma unroll
    for (int ks = 0; ks < 8; ks++) {
        int k0 = ks * 16;
        uint32_t a[2][4], b[8][2];
#pragma unroll
        for (int mt = 0; mt < 2; mt++)
            ldmat4(a[mt], sA + (wm + mt * 16 + (lane & 15)) * P + k0 + (lane >> 4) * 8);
#pragma unroll
        for (int pr = 0; pr < 4; pr++) {
            uint32_t r4[4];
            ldmat4(r4, sB + (wn + pr * 16 + (lane >> 4) * 8 + (lane & 7)) * P
                         + k0 + ((lane >> 3) & 1) * 8);
            b[2 * pr][0] = r4[0]; b[2 * pr][1] = r4[1];
            b[2 * pr + 1][0] = r4[2]; b[2 * pr + 1][1] = r4[3];
        }
#pragma unroll
        for (int mt = 0; mt < 2; mt++)
#pragma unroll
            for (int nt = 0; nt < 8; nt++) mma16816(acc[mt][nt], a[mt], b[nt]);
    }

#pragma unroll
    for (int mt = 0; mt < 2; mt++) {
        int row = wm + mt * 16 + (lane >> 2);
#pragma unroll
        for (int nt = 0; nt < 8; nt++) {
            int col = wn + nt * 8 + (lane & 3) * 2;
            *(__nv_bfloat162*)&g_h1b[(size_t)(n0 + row) * FH + col] =
                __floats2bfloat162_rn(acc[mt][nt][0], acc[mt][nt][1]);
            *(__nv_bfloat162*)&g_h1b[(size_t)(n0 + row + 8) * FH + col] =
                __floats2bfloat162_rn(acc[mt][nt][2], acc[mt][nt][3]);
        }
    }
}

// ---------------- lin2: g_z2b = bf16( a1 @ W2 ), tensor cores --------------
// block tile 64 nodes x 128 cols, K=256; 8 warps, warp tile 32x32.
__global__ void __launch_bounds__(256) k_lin2() {
    constexpr int P = 264;
    extern __shared__ __nv_bfloat16 sm2[];
    __nv_bfloat16* sA = sm2;              // 64  x P
    __nv_bfloat16* sB = sm2 + 64 * P;     // 128 x P

    int t = threadIdx.x;
    int n0 = blockIdx.x * 64;

    for (int v = t; v < 2048; v += 256) {       // A: 64 rows x 32 uint4
        int r = v >> 5, m = v & 31;
        *(uint4*)&sA[r * P + m * 8] =
            *(const uint4*)&g_a1b[(size_t)(n0 + r) * FH + m * 8];
    }
    for (int v = t; v < 4096; v += 256) {       // B: w2t 128 rows x 32 uint4
        int r = v >> 5, m = v & 31;
        *(uint4*)&sB[r * P + m * 8] = ((const uint4*)g_w2t)[v];
    }
    __syncthreads();

    int lane = t & 31, w = t >> 5;
    int wm = (w & 1) * 32, wn = (w >> 1) * 32;

    float acc[2][4][4] = {};
#pragma unroll
    for (int ks = 0; ks < 16; ks++) {
        int k0 = ks * 16;
        uint32_t a[2][4], b[4][2];
#pragma unroll
        for (int mt = 0; mt < 2; mt++)
            ldmat4(a[mt], sA + (wm + mt * 16 + (lane & 15)) * P + k0 + (lane >> 4) * 8);
#pragma unroll
        for (int pr = 0; pr < 2; pr++) {
            uint32_t r4[4];
            ldmat4(r4, sB + (wn + pr * 16 + (lane >> 4) * 8 + (lane & 7)) * P
                         + k0 + ((lane >> 3) & 1) * 8);
            b[2 * pr][0] = r4[0]; b[2 * pr][1] = r4[1];
            b[2 * pr + 1][0] = r4[2]; b[2 * pr + 1][1] = r4[3];
        }
#pragma unroll
        for (int mt = 0; mt < 2; mt++)
#pragma unroll
            for (int nt = 0; nt < 4; nt++) mma16816(acc[mt][nt], a[mt], b[nt]);
    }

#pragma unroll
    for (int mt = 0; mt < 2; mt++) {
        int row = wm + mt * 16 + (lane >> 2);
#pragma unroll
        for (int nt = 0; nt < 4; nt++) {
            int col = wn + nt * 8 + (lane & 3) * 2;
            *(__nv_bfloat162*)&g_z2b[(size_t)(n0 + row) * FO + col] =
                __floats2bfloat162_rn(acc[mt][nt][0], acc[mt][nt][1]);
            *(__nv_bfloat162*)&g_z2b[(size_t)(n0 + row + 8) * FO + col] =
                __floats2bfloat162_rn(acc[mt][nt][2], acc[mt][nt][3]);
        }
    }
}

// ---------------- GCN aggregation, layer 1 (bf16x2 gathers, fp32 accum) ----
__global__ void __launch_bounds__(128) k_agg1(const float* __restrict__ bias) {
    const __nv_bfloat162* __restrict__ H = (const __nv_bfloat162*)g_h1b;
    int d = blockIdx.x;
    int t = threadIdx.x;          // handles features 2t, 2t+1
    int i = g_rowstart[d], end = g_rowstart[d + 1];
    float ax = 0.f, ay = 0.f;
    for (; i + 4 <= end; i += 4) {
        int s0 = g_src[i], s1 = g_src[i + 1], s2 = g_src[i + 2], s3 = g_src[i + 3];
        float w0 = g_dinv[s0], w1 = g_dinv[s1], w2 = g_dinv[s2], w3 = g_dinv[s3];
        float2 f0 = __bfloat1622float2(H[s0 * 128 + t]);
        float2 f1 = __bfloat1622float2(H[s1 * 128 + t]);
        float2 f2 = __bfloat1622float2(H[s2 * 128 + t]);
        float2 f3 = __bfloat1622float2(H[s3 * 128 + t]);
        ax += w0 * f0.x + w1 * f1.x + w2 * f2.x + w3 * f3.x;
        ay += w0 * f0.y + w1 * f1.y + w2 * f2.y + w3 * f3.y;
    }
    for (; i < end; i++) {
        int s0 = g_src[i];
        float w0 = g_dinv[s0];
        float2 f0 = __bfloat1622float2(H[s0 * 128 + t]);
        ax += w0 * f0.x;
        ay += w0 * f0.y;
    }
    float dd = g_dinv[d];
    float2 hs = __bfloat1622float2(H[d * 128 + t]);
    float2 bb = ((const float2*)bias)[t];
    float rx = fmaf(dd, ax, dd * dd * hs.x) + bb.x;
    float ry = fmaf(dd, ay, dd * dd * hs.y) + bb.y;
    ((__nv_bfloat162*)g_a1b)[d * 128 + t] =
        __floats2bfloat162_rn(fmaxf(rx, 0.f), fmaxf(ry, 0.f));
}

// ---------------- GCN aggregation, layer 2 ----------------------------------
__global__ void __launch_bounds__(64) k_agg2(const float* __restrict__ bias) {
    const __nv_bfloat162* __restrict__ Z = (const __nv_bfloat162*)g_z2b;
    int d = blockIdx.x;
    int t = threadIdx.x;          // handles features 2t, 2t+1 (64 threads)
    int i = g_rowstart[d], end = g_rowstart[d + 1];
    float ax = 0.f, ay = 0.f;
    for (; i + 4 <= end; i += 4) {
        int s0 = g_src[i], s1 = g_src[i + 1], s2 = g_src[i + 2], s3 = g_src[i + 3];
        float w0 = g_dinv[s0], w1 = g_dinv[s1], w2 = g_dinv[s2], w3 = g_dinv[s3];
        float2 f0 = __bfloat1622float2(Z[s0 * 64 + t]);
        float2 f1 = __bfloat1622float2(Z[s1 * 64 + t]);
        float2 f2 = __bfloat1622float2(Z[s2 * 64 + t]);
        float2 f3 = __bfloat1622float2(Z[s3 * 64 + t]);
        ax += w0 * f0.x + w1 * f1.x + w2 * f2.x + w3 * f3.x;
        ay += w0 * f0.y + w1 * f1.y + w2 * f2.y + w3 * f3.y;
    }
    for (; i < end; i++) {
        int s0 = g_src[i];
        float w0 = g_dinv[s0];
        float2 f0 = __bfloat1622float2(Z[s0 * 64 + t]);
        ax += w0 * f0.x;
        ay += w0 * f0.y;
    }
    float dd = g_dinv[d];
    float2 zs = __bfloat1622float2(Z[d * 64 + t]);
    float2 bb = ((const float2*)bias)[t];
    float rx = fmaf(dd, ax, dd * dd * zs.x) + bb.x;
    float ry = fmaf(dd, ay, dd * dd * zs.y) + bb.y;
    ((__nv_bfloat162*)g_zb)[d * 64 + t] = __floats2bfloat162_rn(rx, ry);
}

// ---------------- decode: out = sigmoid(z @ z^T), bf16 mma, symmetric ------
// sigmoid(x) = 0.5*tanh(x/2) + 0.5  (1 MUFU + 2 FMA; replaces exp + full div)
__device__ __forceinline__ float sigmoidf_(float v) {
    float th;
    asm("tanh.approx.f32 %0, %1;" : "=f"(th) : "f"(v * 0.5f));
    return fmaf(th, 0.5f, 0.5f);
}

__device__ __forceinline__ void bulk_store_row(void* gptr, uint32_t saddr, int bytes) {
    asm volatile("cp.async.bulk.global.shared::cta.bulk_group [%0], [%1], %2;"
                 :: "l"(gptr), "r"(saddr), "r"(bytes) : "memory");
}

__global__ void __launch_bounds__(256, 2) k_decode(float* __restrict__ out) {
    int bi = blockIdx.y, bj = blockIdx.x;
    if (bj < bi) return;

    constexpr int P  = 136;  // bf16 pitch for MMA tiles
    constexpr int PF = 136;  // fp32 pitch for output staging (128*136*4 = 69632)
    extern __shared__ __nv_bfloat16 sm[];
    __nv_bfloat16* sA = sm;
    __nv_bfloat16* sB = sm + 128 * P;
    float* sf = (float*)sm;  // reused after MMA

    int t  = threadIdx.x;
    int i0 = bi * 128;
    int j0 = bj * 128;

    for (int v = t; v < 4096; v += 256) {
        int which = v >> 11;               // 0 = A, 1 = B
        int r = (v >> 4) & 127;
        int c = (v & 15) * 8;
        const __nv_bfloat16* srcp = g_zb + (size_t)((which ? j0 : i0) + r) * FO + c;
        __nv_bfloat16* dstp = (which ? sB : sA) + r * P + c;
        *(uint4*)dstp = *(const uint4*)srcp;
    }
    __syncthreads();

    int lane = t & 31, w = t >> 5;
    int wm = (w & 3) * 32;
    int wn = (w >> 2) * 64;

    float acc[2][8][4] = {};
#pragma unroll
    for (int ks = 0; ks < 8; ks++) {
        int k0 = ks * 16;
        uint32_t a[2][4], b[8][2];
#pragma unroll
        for (int mt = 0; mt < 2; mt++)
            ldmat4(a[mt], sA + (wm + mt * 16 + (lane & 15)) * P + k0 + (lane >> 4) * 8);
#pragma unroll
        for (int pr = 0; pr < 4; pr++) {
            uint32_t r4[4];
            ldmat4(r4, sB + (wn + pr * 16 + (lane >> 4) * 8 + (lane & 7)) * P
                         + k0 + ((lane >> 3) & 1) * 8);
            b[2 * pr][0] = r4[0]; b[2 * pr][1] = r4[1];
            b[2 * pr + 1][0] = r4[2]; b[2 * pr + 1][1] = r4[3];
        }
#pragma unroll
        for (int mt = 0; mt < 2; mt++)
#pragma unroll
            for (int nt = 0; nt < 8; nt++) mma16816(acc[mt][nt], a[mt], b[nt]);
    }

#pragma unroll
    for (int mt = 0; mt < 2; mt++)
#pragma unroll
        for (int nt = 0; nt < 8; nt++)
#pragma unroll
            for (int q = 0; q < 4; q++) acc[mt][nt][q] = sigmoidf_(acc[mt][nt][q]);

    bool diag = (bi == bj);
    __syncthreads();  // all warps done reading sA/sB before staging reuses it

    // pass 1: direct tile, row-major staging, bulk-store 128 rows
    int r0b = wm + (lane >> 2);
#pragma unroll
    for (int mt = 0; mt < 2; mt++) {
        int r0 = r0b + mt * 16;
#pragma unroll
        for (int nt = 0; nt < 8; nt++) {
            int c0 = wn + nt * 8 + (lane & 3) * 2;
            *(float2*)&sf[r0 * PF + c0]       = make_float2(acc[mt][nt][0], acc[mt][nt][1]);
            *(float2*)&sf[(r0 + 8) * PF + c0] = make_float2(acc[mt][nt][2], acc[mt][nt][3]);
        }
    }
    __syncthreads();
    if (t < 128) {
        asm volatile("fence.proxy.async.shared::cta;" ::: "memory");
        bulk_store_row(out + (size_t)(i0 + t) * NN + j0, smem_u32(&sf[t * PF]), 512);
        asm volatile("cp.async.bulk.commit_group;" ::: "memory");
        asm volatile("cp.async.bulk.wait_group.read 0;" ::: "memory");
    }
    __syncthreads();

    // pass 2: mirror tile (transposed), bulk-store 128 rows
    if (!diag) {
#pragma unroll
        for (int mt = 0; mt < 2; mt++) {
            int r0 = r0b + mt * 16;
#pragma unroll
            for (int nt = 0; nt < 8; nt++) {
                int c0 = wn + nt * 8 + (lane & 3) * 2;
                sf[c0 * PF + r0]           = acc[mt][nt][0];
                sf[(c0 + 1) * PF + r0]     = acc[mt][nt][1];
                sf[c0 * PF + r0 + 8]       = acc[mt][nt][2];
                sf[(c0 + 1) * PF + r0 + 8] = acc[mt][nt][3];
            }
        }
        __syncthreads();
        if (t < 128) {
            asm volatile("fence.proxy.async.shared::cta;" ::: "memory");
            bulk_store_row(out + (size_t)(j0 + t) * NN + i0, smem_u32(&sf[t * PF]), 512);
            asm volatile("cp.async.bulk.commit_group;" ::: "memory");
            asm volatile("cp.async.bulk.wait_group.read 0;" ::: "memory");
        }
        __syncthreads();
    }
}

// ---------------- launch ----------------------------------------------------
extern "C" void kernel_launch(void* const* d_in, const int* in_sizes, int n_in,
                              void* d_out, int out_size) {
    const int*   x   = (const int*)d_in[0];
    const int*   ei  = (const int*)d_in[1];   // [2, E]: src then dst
    const float* emb = (const float*)d_in[2];
    const float* W1  = (const float*)d_in[3];
    const float* b1  = (const float*)d_in[4];
    const float* W2  = (const float*)d_in[5];
    const float* b2  = (const float*)d_in[6];
    float* out = (float*)d_out;

    const int* src = ei;
    const int* dst = ei + EE;

    const int smem_dec  = 128 * 136 * (int)sizeof(float);                // 69632
    const int smem_lin1 = (64 + 256) * 136 * (int)sizeof(__nv_bfloat16); // 87040
    const int smem_lin2 = (64 + 128) * 264 * (int)sizeof(__nv_bfloat16); // 101376
    cudaFuncSetAttribute(k_decode, cudaFuncAttributeMaxDynamicSharedMemorySize, smem_dec);
    cudaFuncSetAttribute(k_lin1,   cudaFuncAttributeMaxDynamicSharedMemorySize, smem_lin1);
    cudaFuncSetAttribute(k_lin2,   cudaFuncAttributeMaxDynamicSharedMemorySize, smem_lin2);

    k_wconv<<<256, 256>>>(W1, W2);
    k_count<<<EE / 1024, 256>>>(dst);
    k_scan <<<1, 1024>>>();
    k_fill <<<EE / 1024, 256>>>(src, dst);

    k_lin1<<<NN / 64, 256, smem_lin1>>>(x, emb);
    k_agg1<<<NN, 128>>>(b1);
    k_lin2<<<NN / 64, 256, smem_lin2>>>();
    k_agg2<<<NN, 64>>>(b2);

    dim3 grid(NN / 128, NN / 128);
    k_decode<<<grid, 256, smem_dec>>>(out);
}

// round 7
// speedup vs baseline: 2.1269x; 1.2452x over previous
#include <cuda_runtime.h>
#include <cuda_bf16.h>
#include <cstdint>

static constexpr int NN  = 8192;
static constexpr int EE  = 524288;
static constexpr int FIN = 128;
static constexpr int FH  = 256;
static constexpr int FO  = 128;
static constexpr int PAD = 192;   // padded CSR row stride (max degree ~98)

// ---------------- scratch (device globals; no allocation allowed) ----------
__device__ int   g_cnt[NN];          // degree (written by k_dinv each run)
__device__ int   g_cursor[NN];       // zero at entry (BSS / reset by k_dinv)
__device__ int   g_src[NN * PAD];    // padded CSR
__device__ float g_dinv[NN];
__device__ __nv_bfloat16 g_w1t[FH * FIN];   // W1^T bf16  [256][128]
__device__ __nv_bfloat16 g_w2t[FO * FH];    // W2^T bf16  [128][256]
__device__ __nv_bfloat16 g_hb[NN * FIN];    // H = emb[x]          (bf16)
__device__ __nv_bfloat16 g_hab[NN * FIN];   // aggregated H        (bf16)
__device__ __nv_bfloat16 g_a1b[NN * FH];    // relu(gcn1)          (bf16)
__device__ __nv_bfloat16 g_z2b[NN * FO];    // lin2 out            (bf16)
__device__ __nv_bfloat16 g_zb[NN * FO];     // z (gcn2)            (bf16)

// ---------------- weight prep: transpose + bf16 ----------------------------
__global__ void k_wconv(const float* __restrict__ W1, const float* __restrict__ W2) {
    int idx = blockIdx.x * blockDim.x + threadIdx.x;   // 65536 threads
    if (idx < FH * FIN) {
        int j = idx >> 7, k = idx & 127;               // w1t[j][k] = W1[k][j]
        g_w1t[idx] = __float2bfloat16(W1[k * FH + j]);
    } else {
        int i2 = idx - FH * FIN;
        int j = i2 >> 8, k = i2 & 255;                 // w2t[j][k] = W2[k][j]
        g_w2t[i2] = __float2bfloat16(W2[k * FO + j]);
    }
}

// ---------------- embedding gather: g_hb = bf16(emb[x]) --------------------
__global__ void k_gather(const int* __restrict__ x, const float* __restrict__ emb) {
    int idx = blockIdx.x * blockDim.x + threadIdx.x;   // NN*64 threads
    int n = idx >> 6, t = idx & 63;
    float2 f = *(const float2*)(emb + (size_t)x[n] * FIN + t * 2);
    ((__nv_bfloat162*)g_hb)[n * 64 + t] = __floats2bfloat162_rn(f.x, f.y);
}

// ---------------- single-pass padded CSR fill (8 edges / thread) -----------
__global__ void k_fill(const int* __restrict__ src, const int* __restrict__ dst) {
    int e = (blockIdx.x * blockDim.x + threadIdx.x) * 8;
    int4 d0 = *(const int4*)(dst + e);
    int4 d1 = *(const int4*)(dst + e + 4);
    int4 s0 = *(const int4*)(src + e);
    int4 s1 = *(const int4*)(src + e + 4);
    int p0 = atomicAdd(&g_cursor[d0.x], 1);
    int p1 = atomicAdd(&g_cursor[d0.y], 1);
    int p2 = atomicAdd(&g_cursor[d0.z], 1);
    int p3 = atomicAdd(&g_cursor[d0.w], 1);
    int p4 = atomicAdd(&g_cursor[d1.x], 1);
    int p5 = atomicAdd(&g_cursor[d1.y], 1);
    int p6 = atomicAdd(&g_cursor[d1.z], 1);
    int p7 = atomicAdd(&g_cursor[d1.w], 1);
    g_src[d0.x * PAD + p0] = s0.x;
    g_src[d0.y * PAD + p1] = s0.y;
    g_src[d0.z * PAD + p2] = s0.z;
    g_src[d0.w * PAD + p3] = s0.w;
    g_src[d1.x * PAD + p4] = s1.x;
    g_src[d1.y * PAD + p5] = s1.y;
    g_src[d1.z * PAD + p6] = s1.z;
    g_src[d1.w * PAD + p7] = s1.w;
}

// ---------------- degree -> dinv, stash count, reset cursor ----------------
__global__ void k_dinv() {
    int i = blockIdx.x * blockDim.x + threadIdx.x;
    int c = g_cursor[i];
    g_cnt[i]  = c;
    g_dinv[i] = rsqrtf((float)c + 1.0f);   // +1 self loop
    g_cursor[i] = 0;                        // ready for next replay
}

// ---------------- layer-1 pre-aggregation over H (128-wide bf16) -----------
// hab[d] = dinv[d] * sum_s dinv[s]*H[s] + dinv[d]^2 * H[d]
__global__ void __launch_bounds__(64) k_agg0() {
    const __nv_bfloat162* __restrict__ H = (const __nv_bfloat162*)g_hb;
    int d = blockIdx.x;
    int t = threadIdx.x;           // features 2t, 2t+1
    int cnt = g_cnt[d];
    const int* row = g_src + d * PAD;
    float ax = 0.f, ay = 0.f;
    int i = 0;
    for (; i + 4 <= cnt; i += 4) {
        int s0 = row[i], s1 = row[i + 1], s2 = row[i + 2], s3 = row[i + 3];
        float w0 = g_dinv[s0], w1 = g_dinv[s1], w2 = g_dinv[s2], w3 = g_dinv[s3];
        float2 f0 = __bfloat1622float2(H[s0 * 64 + t]);
        float2 f1 = __bfloat1622float2(H[s1 * 64 + t]);
        float2 f2 = __bfloat1622float2(H[s2 * 64 + t]);
        float2 f3 = __bfloat1622float2(H[s3 * 64 + t]);
        ax += w0 * f0.x + w1 * f1.x + w2 * f2.x + w3 * f3.x;
        ay += w0 * f0.y + w1 * f1.y + w2 * f2.y + w3 * f3.y;
    }
    for (; i < cnt; i++) {
        int s0 = row[i];
        float w0 = g_dinv[s0];
        float2 f0 = __bfloat1622float2(H[s0 * 64 + t]);
        ax += w0 * f0.x;
        ay += w0 * f0.y;
    }
    float dd = g_dinv[d];
    float2 hs = __bfloat1622float2(H[d * 64 + t]);
    float rx = fmaf(dd, ax, dd * dd * hs.x);
    float ry = fmaf(dd, ay, dd * dd * hs.y);
    ((__nv_bfloat162*)g_hab)[d * 64 + t] = __floats2bfloat162_rn(rx, ry);
}

// ---------------- shared mma helpers ----------------------------------------
__device__ __forceinline__ uint32_t smem_u32(const void* p) {
    return (uint32_t)__cvta_generic_to_shared(p);
}

__device__ __forceinline__ void ldmat4(uint32_t* r, const __nv_bfloat16* p) {
    asm volatile("ldmatrix.sync.aligned.m8n8.x4.shared.b16 {%0,%1,%2,%3}, [%4];"
                 : "=r"(r[0]), "=r"(r[1]), "=r"(r[2]), "=r"(r[3])
                 : "r"(smem_u32(p)));
}

__device__ __forceinline__ void mma16816(float* c, const uint32_t* a, const uint32_t* b) {
    asm volatile("mma.sync.aligned.m16n8k16.row.col.f32.bf16.bf16.f32 "
                 "{%0,%1,%2,%3}, {%4,%5,%6,%7}, {%8,%9}, {%0,%1,%2,%3};"
                 : "+f"(c[0]), "+f"(c[1]), "+f"(c[2]), "+f"(c[3])
                 : "r"(a[0]), "r"(a[1]), "r"(a[2]), "r"(a[3]), "r"(b[0]), "r"(b[1]));
}

// ---------------- lin1: a1 = relu( hab @ W1 + b1 ), tensor cores -----------
// block tile 64 nodes x 256 cols, K=128; 8 warps, warp tile 32x64.
__global__ void __launch_bounds__(256) k_lin1(const float* __restrict__ b1) {
    constexpr int P = 136;
    extern __shared__ __nv_bfloat16 sm1[];
    __nv_bfloat16* sA = sm1;              // 64  x P
    __nv_bfloat16* sB = sm1 + 64 * P;     // 256 x P

    int t = threadIdx.x;
    int n0 = blockIdx.x * 64;

    for (int v = t; v < 1024; v += 256) {       // A: 64 rows x 16 uint4
        int r = v >> 4, m = v & 15;
        *(uint4*)&sA[r * P + m * 8] =
            *(const uint4*)&g_hab[(size_t)(n0 + r) * FIN + m * 8];
    }
    for (int v = t; v < 4096; v += 256) {       // B: w1t 256 rows x 16 uint4
        int r = v >> 4, m = v & 15;
        *(uint4*)&sB[r * P + m * 8] = ((const uint4*)g_w1t)[v];
    }
    __syncthreads();

    int lane = t & 31, w = t >> 5;
    int wm = (w & 1) * 32, wn = (w >> 1) * 64;

    float acc[2][8][4] = {};
#pragma unroll
    for (int ks = 0; ks < 8; ks++) {
        int k0 = ks * 16;
        uint32_t a[2][4], b[8][2];
#pragma unroll
        for (int mt = 0; mt < 2; mt++)
            ldmat4(a[mt], sA + (wm + mt * 16 + (lane & 15)) * P + k0 + (lane >> 4) * 8);
#pragma unroll
        for (int pr = 0; pr < 4; pr++) {
            uint32_t r4[4];
            ldmat4(r4, sB + (wn + pr * 16 + (lane >> 4) * 8 + (lane & 7)) * P
                         + k0 + ((lane >> 3) & 1) * 8);
            b[2 * pr][0] = r4[0]; b[2 * pr][1] = r4[1];
            b[2 * pr + 1][0] = r4[2]; b[2 * pr + 1][1] = r4[3];
        }
#pragma unroll
        for (int mt = 0; mt < 2; mt++)
#pragma unroll
            for (int nt = 0; nt < 8; nt++) mma16816(acc[mt][nt], a[mt], b[nt]);
    }

#pragma unroll
    for (int mt = 0; mt < 2; mt++) {
        int row = wm + mt * 16 + (lane >> 2);
#pragma unroll
        for (int nt = 0; nt < 8; nt++) {
            int col = wn + nt * 8 + (lane & 3) * 2;
            float2 bb = *(const float2*)(b1 + col);
            float v0 = fmaxf(acc[mt][nt][0] + bb.x, 0.f);
            float v1 = fmaxf(acc[mt][nt][1] + bb.y, 0.f);
            float v2 = fmaxf(acc[mt][nt][2] + bb.x, 0.f);
            float v3 = fmaxf(acc[mt][nt][3] + bb.y, 0.f);
            *(__nv_bfloat162*)&g_a1b[(size_t)(n0 + row) * FH + col] =
                __floats2bfloat162_rn(v0, v1);
            *(__nv_bfloat162*)&g_a1b[(size_t)(n0 + row + 8) * FH + col] =
                __floats2bfloat162_rn(v2, v3);
        }
    }
}

// ---------------- lin2: g_z2b = bf16( a1 @ W2 ), tensor cores --------------
// block tile 64 nodes x 128 cols, K=256; 8 warps, warp tile 32x32.
__global__ void __launch_bounds__(256) k_lin2() {
    constexpr int P = 264;
    extern __shared__ __nv_bfloat16 sm2[];
    __nv_bfloat16* sA = sm2;              // 64  x P
    __nv_bfloat16* sB = sm2 + 64 * P;     // 128 x P

    int t = threadIdx.x;
    int n0 = blockIdx.x * 64;

    for (int v = t; v < 2048; v += 256) {       // A: 64 rows x 32 uint4
        int r = v >> 5, m = v & 31;
        *(uint4*)&sA[r * P + m * 8] =
            *(const uint4*)&g_a1b[(size_t)(n0 + r) * FH + m * 8];
    }
    for (int v = t; v < 4096; v += 256) {       // B: w2t 128 rows x 32 uint4
        int r = v >> 5, m = v & 31;
        *(uint4*)&sB[r * P + m * 8] = ((const uint4*)g_w2t)[v];
    }
    __syncthreads();

    int lane = t & 31, w = t >> 5;
    int wm = (w & 1) * 32, wn = (w >> 1) * 32;

    float acc[2][4][4] = {};
#pragma unroll
    for (int ks = 0; ks < 16; ks++) {
        int k0 = ks * 16;
        uint32_t a[2][4], b[4][2];
#pragma unroll
        for (int mt = 0; mt < 2; mt++)
            ldmat4(a[mt], sA + (wm + mt * 16 + (lane & 15)) * P + k0 + (lane >> 4) * 8);
#pragma unroll
        for (int pr = 0; pr < 2; pr++) {
            uint32_t r4[4];
            ldmat4(r4, sB + (wn + pr * 16 + (lane >> 4) * 8 + (lane & 7)) * P
                         + k0 + ((lane >> 3) & 1) * 8);
            b[2 * pr][0] = r4[0]; b[2 * pr][1] = r4[1];
            b[2 * pr + 1][0] = r4[2]; b[2 * pr + 1][1] = r4[3];
        }
#pragma unroll
        for (int mt = 0; mt < 2; mt++)
#pragma unroll
            for (int nt = 0; nt < 4; nt++) mma16816(acc[mt][nt], a[mt], b[nt]);
    }

#pragma unroll
    for (int mt = 0; mt < 2; mt++) {
        int row = wm + mt * 16 + (lane >> 2);
#pragma unroll
        for (int nt = 0; nt < 4; nt++) {
            int col = wn + nt * 8 + (lane & 3) * 2;
            *(__nv_bfloat162*)&g_z2b[(size_t)(n0 + row) * FO + col] =
                __floats2bfloat162_rn(acc[mt][nt][0], acc[mt][nt][1]);
            *(__nv_bfloat162*)&g_z2b[(size_t)(n0 + row + 8) * FO + col] =
                __floats2bfloat162_rn(acc[mt][nt][2], acc[mt][nt][3]);
        }
    }
}

// ---------------- GCN aggregation, layer 2 (bf16x2 gathers) -----------------
__global__ void __launch_bounds__(64) k_agg2(const float* __restrict__ bias) {
    const __nv_bfloat162* __restrict__ Z = (const __nv_bfloat162*)g_z2b;
    int d = blockIdx.x;
    int t = threadIdx.x;           // features 2t, 2t+1
    int cnt = g_cnt[d];
    const int* row = g_src + d * PAD;
    float ax = 0.f, ay = 0.f;
    int i = 0;
    for (; i + 4 <= cnt; i += 4) {
        int s0 = row[i], s1 = row[i + 1], s2 = row[i + 2], s3 = row[i + 3];
        float w0 = g_dinv[s0], w1 = g_dinv[s1], w2 = g_dinv[s2], w3 = g_dinv[s3];
        float2 f0 = __bfloat1622float2(Z[s0 * 64 + t]);
        float2 f1 = __bfloat1622float2(Z[s1 * 64 + t]);
        float2 f2 = __bfloat1622float2(Z[s2 * 64 + t]);
        float2 f3 = __bfloat1622float2(Z[s3 * 64 + t]);
        ax += w0 * f0.x + w1 * f1.x + w2 * f2.x + w3 * f3.x;
        ay += w0 * f0.y + w1 * f1.y + w2 * f2.y + w3 * f3.y;
    }
    for (; i < cnt; i++) {
        int s0 = row[i];
        float w0 = g_dinv[s0];
        float2 f0 = __bfloat1622float2(Z[s0 * 64 + t]);
        ax += w0 * f0.x;
        ay += w0 * f0.y;
    }
    float dd = g_dinv[d];
    float2 zs = __bfloat1622float2(Z[d * 64 + t]);
    float2 bb = ((const float2*)bias)[t];
    float rx = fmaf(dd, ax, dd * dd * zs.x) + bb.x;
    float ry = fmaf(dd, ay, dd * dd * zs.y) + bb.y;
    ((__nv_bfloat162*)g_zb)[d * 64 + t] = __floats2bfloat162_rn(rx, ry);
}

// ---------------- decode: out = sigmoid(z @ z^T), bf16 mma, symmetric ------
__device__ __forceinline__ float sigmoidf_(float v) {
    float th;
    asm("tanh.approx.f32 %0, %1;" : "=f"(th) : "f"(v * 0.5f));
    return fmaf(th, 0.5f, 0.5f);
}

__device__ __forceinline__ void bulk_store_row(void* gptr, uint32_t saddr, int bytes) {
    asm volatile("cp.async.bulk.global.shared::cta.bulk_group [%0], [%1], %2;"
                 :: "l"(gptr), "r"(saddr), "r"(bytes) : "memory");
}

__global__ void __launch_bounds__(256, 2) k_decode(float* __restrict__ out) {
    int bi = blockIdx.y, bj = blockIdx.x;
    if (bj < bi) return;

    constexpr int P  = 136;  // bf16 pitch for MMA tiles
    constexpr int PF = 136;  // fp32 pitch for output staging (128*136*4 = 69632)
    extern __shared__ __nv_bfloat16 sm[];
    __nv_bfloat16* sA = sm;
    __nv_bfloat16* sB = sm + 128 * P;
    float* sf = (float*)sm;  // reused after MMA

    int t  = threadIdx.x;
    int i0 = bi * 128;
    int j0 = bj * 128;

    for (int v = t; v < 4096; v += 256) {
        int which = v >> 11;               // 0 = A, 1 = B
        int r = (v >> 4) & 127;
        int c = (v & 15) * 8;
        const __nv_bfloat16* srcp = g_zb + (size_t)((which ? j0 : i0) + r) * FO + c;
        __nv_bfloat16* dstp = (which ? sB : sA) + r * P + c;
        *(uint4*)dstp = *(const uint4*)srcp;
    }
    __syncthreads();

    int lane = t & 31, w = t >> 5;
    int wm = (w & 3) * 32;
    int wn = (w >> 2) * 64;

    float acc[2][8][4] = {};
#pragma unroll
    for (int ks = 0; ks < 8; ks++) {
        int k0 = ks * 16;
        uint32_t a[2][4], b[8][2];
#pragma unroll
        for (int mt = 0; mt < 2; mt++)
            ldmat4(a[mt], sA + (wm + mt * 16 + (lane & 15)) * P + k0 + (lane >> 4) * 8);
#pragma unroll
        for (int pr = 0; pr < 4; pr++) {
            uint32_t r4[4];
            ldmat4(r4, sB + (wn + pr * 16 + (lane >> 4) * 8 + (lane & 7)) * P
                         + k0 + ((lane >> 3) & 1) * 8);
            b[2 * pr][0] = r4[0]; b[2 * pr][1] = r4[1];
            b[2 * pr + 1][0] = r4[2]; b[2 * pr + 1][1] = r4[3];
        }
#pragma unroll
        for (int mt = 0; mt < 2; mt++)
#pragma unroll
            for (int nt = 0; nt < 8; nt++) mma16816(acc[mt][nt], a[mt], b[nt]);
    }

#pragma unroll
    for (int mt = 0; mt < 2; mt++)
#pragma unroll
        for (int nt = 0; nt < 8; nt++)
#pragma unroll
            for (int q = 0; q < 4; q++) acc[mt][nt][q] = sigmoidf_(acc[mt][nt][q]);

    bool diag = (bi == bj);
    __syncthreads();  // all warps done reading sA/sB before staging reuses it

    // pass 1: direct tile, row-major staging, bulk-store 128 rows
    int r0b = wm + (lane >> 2);
#pragma unroll
    for (int mt = 0; mt < 2; mt++) {
        int r0 = r0b + mt * 16;
#pragma unroll
        for (int nt = 0; nt < 8; nt++) {
            int c0 = wn + nt * 8 + (lane & 3) * 2;
            *(float2*)&sf[r0 * PF + c0]       = make_float2(acc[mt][nt][0], acc[mt][nt][1]);
            *(float2*)&sf[(r0 + 8) * PF + c0] = make_float2(acc[mt][nt][2], acc[mt][nt][3]);
        }
    }
    __syncthreads();
    if (t < 128) {
        asm volatile("fence.proxy.async.shared::cta;" ::: "memory");
        bulk_store_row(out + (size_t)(i0 + t) * NN + j0, smem_u32(&sf[t * PF]), 512);
        asm volatile("cp.async.bulk.commit_group;" ::: "memory");
        asm volatile("cp.async.bulk.wait_group.read 0;" ::: "memory");
    }
    __syncthreads();

    // pass 2: mirror tile (transposed), bulk-store 128 rows
    if (!diag) {
#pragma unroll
        for (int mt = 0; mt < 2; mt++) {
            int r0 = r0b + mt * 16;
#pragma unroll
            for (int nt = 0; nt < 8; nt++) {
                int c0 = wn + nt * 8 + (lane & 3) * 2;
                sf[c0 * PF + r0]           = acc[mt][nt][0];
                sf[(c0 + 1) * PF + r0]     = acc[mt][nt][1];
                sf[c0 * PF + r0 + 8]       = acc[mt][nt][2];
                sf[(c0 + 1) * PF + r0 + 8] = acc[mt][nt][3];
            }
        }
        __syncthreads();
        if (t < 128) {
            asm volatile("fence.proxy.async.shared::cta;" ::: "memory");
            bulk_store_row(out + (size_t)(j0 + t) * NN + i0, smem_u32(&sf[t * PF]), 512);
            asm volatile("cp.async.bulk.commit_group;" ::: "memory");
            asm volatile("cp.async.bulk.wait_group.read 0;" ::: "memory");
        }
        __syncthreads();
    }
}

// ---------------- launch ----------------------------------------------------
extern "C" void kernel_launch(void* const* d_in, const int* in_sizes, int n_in,
                              void* d_out, int out_size) {
    const int*   x   = (const int*)d_in[0];
    const int*   ei  = (const int*)d_in[1];   // [2, E]: src then dst
    const float* emb = (const float*)d_in[2];
    const float* b1  = (const float*)d_in[4];
    const float* W1  = (const float*)d_in[3];
    const float* W2  = (const float*)d_in[5];
    const float* b2  = (const float*)d_in[6];
    float* out = (float*)d_out;

    const int* src = ei;
    const int* dst = ei + EE;

    const int smem_dec  = 128 * 136 * (int)sizeof(float);                // 69632
    const int smem_lin1 = (64 + 256) * 136 * (int)sizeof(__nv_bfloat16); // 87040
    const int smem_lin2 = (64 + 128) * 264 * (int)sizeof(__nv_bfloat16); // 101376
    cudaFuncSetAttribute(k_decode, cudaFuncAttributeMaxDynamicSharedMemorySize, smem_dec);
    cudaFuncSetAttribute(k_lin1,   cudaFuncAttributeMaxDynamicSharedMemorySize, smem_lin1);
    cudaFuncSetAttribute(k_lin2,   cudaFuncAttributeMaxDynamicSharedMemorySize, smem_lin2);

    k_wconv <<<256, 256>>>(W1, W2);
    k_gather<<<NN * 64 / 256, 256>>>(x, emb);
    k_fill  <<<EE / 2048, 256>>>(src, dst);
    k_dinv  <<<NN / 256, 256>>>();

    k_agg0<<<NN, 64>>>();
    k_lin1<<<NN / 64, 256, smem_lin1>>>(b1);
    k_lin2<<<NN / 64, 256, smem_lin2>>>();
    k_agg2<<<NN, 64>>>(b2);

    dim3 grid(NN / 128, NN / 128);
    k_decode<<<grid, 256, smem_dec>>>(out);
}